// round 3
// baseline (speedup 1.0000x reference)
#include <cuda_runtime.h>
#include <math.h>

#define NB    64
#define NL    512
#define ND    128
#define TOKS  32768          // B*L per stream
#define NTOK  65536          // 2*B*L
#define NHB   256            // 2*B*H attention batches

// ---------------- scratch (device globals; no allocation allowed) ----------------
__device__ int   g_cnt[NTOK * 2];
__device__ float g_W[ND * ND];
__device__ float g_biasT[ND];
__device__ float g_T2[513 * ND];
__device__ float g_X[(size_t)NTOK * ND];
__device__ float g_H[(size_t)NTOK * ND];
__device__ float g_QKV[(size_t)NTOK * 3 * ND];
__device__ float g_S[(size_t)NHB * NL * NL];
__device__ float g_CTX[(size_t)NTOK * ND];
__device__ float g_FF[(size_t)NTOK * 4 * ND];

// in-kernel scratch-buffer selector (avoids any host-side symbol queries)
#define BUF_X    0
#define BUF_H    1
#define BUF_QKV  2
#define BUF_CTX  3
#define BUF_FF   4
__device__ __forceinline__ float* buf(int id) {
    switch (id) {
        case BUF_X:   return g_X;
        case BUF_H:   return g_H;
        case BUF_QKV: return g_QKV;
        case BUF_CTX: return g_CTX;
        default:      return g_FF;
    }
}

// ---------------- tiny precompute kernels ----------------
// W = w2 @ proj_w  (128x128)
__global__ void k_W(const float* __restrict__ w2, const float* __restrict__ proj_w) {
    int k = blockIdx.x, d = threadIdx.x;
    float acc = 0.f;
    #pragma unroll 8
    for (int j = 0; j < ND; j++) acc += w2[k * ND + j] * proj_w[j * ND + d];
    g_W[k * ND + d] = acc;
}

// biasT = 2*b2 @ proj_w + proj_b
__global__ void k_bias(const float* __restrict__ b2, const float* __restrict__ proj_w,
                       const float* __restrict__ proj_b) {
    int d = threadIdx.x;
    float acc = proj_b[d];
    #pragma unroll 8
    for (int k = 0; k < ND; k++) acc += 2.f * b2[k] * proj_w[k * ND + d];
    g_biasT[d] = acc;
}

// T2[c] = relu(c*w1 + b1) @ W + 0.5*biasT   (c = 0..512)
__global__ void k_table(const float* __restrict__ w1, const float* __restrict__ b1) {
    __shared__ float h[ND];
    int c = blockIdx.x, d = threadIdx.x;
    h[d] = fmaxf((float)c * w1[d] + b1[d], 0.f);
    __syncthreads();
    float acc = 0.5f * g_biasT[d];
    #pragma unroll 8
    for (int k = 0; k < ND; k++) acc += h[k] * g_W[k * ND + d];
    g_T2[c * ND + d] = acc;
}

// ---------------- co-occurrence counts ----------------
__global__ void k_cooc(const int* __restrict__ src, const int* __restrict__ dst) {
    __shared__ int ss[NL], dd[NL];
    int b = blockIdx.x, i = threadIdx.x;
    ss[i] = src[b * NL + i];
    dd[i] = dst[b * NL + i];
    __syncthreads();
    int qs = ss[i], qd = dd[i];
    int css = 0, csd = 0, cds = 0, cdd = 0;
    #pragma unroll 8
    for (int j = 0; j < NL; j++) {
        int s = ss[j], t = dd[j];
        css += (qs == s); csd += (qs == t);
        cds += (qd == s); cdd += (qd == t);
    }
    if (qs == 0) { css = 0; csd = 0; }
    if (qd == 0) { cds = 0; cdd = 0; }
    int ts = b * NL + i, td = TOKS + b * NL + i;
    g_cnt[ts * 2 + 0] = css; g_cnt[ts * 2 + 1] = csd;
    g_cnt[td * 2 + 0] = cds; g_cnt[td * 2 + 1] = cdd;
}

// feat[t][d] = T2[c0][d] + T2[c1][d]
__global__ void k_feat() {
    int idx = blockIdx.x * 256 + threadIdx.x;
    int t = idx >> 7, d = idx & 127;
    int c0 = g_cnt[t * 2], c1 = g_cnt[t * 2 + 1];
    g_X[idx] = g_T2[c0 * ND + d] + g_T2[c1 * ND + d];
}

// ---------------- layernorm (1 row of 128 per block) ----------------
__global__ void k_ln(int xid, int yid,
                     const float* __restrict__ g, const float* __restrict__ b) {
    const float* x = buf(xid);
    float* y = buf(yid);
    int row = blockIdx.x, t = threadIdx.x;
    float v = x[(size_t)row * ND + t];
    __shared__ float sh[4];
    // mean
    float s = v;
    for (int o = 16; o; o >>= 1) s += __shfl_xor_sync(0xffffffffu, s, o);
    int w = t >> 5;
    if ((t & 31) == 0) sh[w] = s;
    __syncthreads();
    float mu = (sh[0] + sh[1] + sh[2] + sh[3]) * (1.f / 128.f);
    __syncthreads();
    // variance of (v - mu)
    float dlt = v - mu;
    float s2 = dlt * dlt;
    for (int o = 16; o; o >>= 1) s2 += __shfl_xor_sync(0xffffffffu, s2, o);
    if ((t & 31) == 0) sh[w] = s2;
    __syncthreads();
    float var = (sh[0] + sh[1] + sh[2] + sh[3]) * (1.f / 128.f);
    float r = rsqrtf(var + 1e-5f);
    y[(size_t)row * ND + t] = dlt * r * g[t] + b[t];
}

// ---------------- generic fp32 tiled NN GEMM: C = act(A@B + bias) + res ----------------
// A, C, res are scratch-buffer ids (resid < 0 -> none; cext non-null overrides C).
// A: M x K (lda=K), B: K x N (ldb=N), C/res: M x N (ldc=N). 64x64 tile, BK=16, 256 thr, 4x4/thr.
__global__ void gemm_nn(int Aid, const float* __restrict__ Bm,
                        const float* __restrict__ bias, int resid,
                        int Cid, float* __restrict__ cext,
                        int M, int N, int K, int act) {
    const float* A = buf(Aid);
    const float* res = (resid >= 0) ? buf(resid) : nullptr;
    float* C = cext ? cext : buf(Cid);
    __shared__ float As[16][64];
    __shared__ float Bs[16][64];
    int tid = threadIdx.x;
    int tx = tid & 15, ty = tid >> 4;
    int bm = blockIdx.y * 64, bn = blockIdx.x * 64;
    int ar = tid >> 2, ac = (tid & 3) * 4;
    int br = tid >> 4, bc = (tid & 15) * 4;
    float acc[4][4] = {};
    for (int k0 = 0; k0 < K; k0 += 16) {
        float4 a = *(const float4*)&A[(size_t)(bm + ar) * K + k0 + ac];
        As[ac + 0][ar] = a.x; As[ac + 1][ar] = a.y;
        As[ac + 2][ar] = a.z; As[ac + 3][ar] = a.w;
        *(float4*)&Bs[br][bc] = *(const float4*)&Bm[(size_t)(k0 + br) * N + bn + bc];
        __syncthreads();
        #pragma unroll
        for (int k = 0; k < 16; k++) {
            float av[4], bv[4];
            *(float4*)av = *(float4*)&As[k][ty * 4];
            *(float4*)bv = *(float4*)&Bs[k][tx * 4];
            #pragma unroll
            for (int i = 0; i < 4; i++)
                #pragma unroll
                for (int j = 0; j < 4; j++) acc[i][j] += av[i] * bv[j];
        }
        __syncthreads();
    }
    #pragma unroll
    for (int i = 0; i < 4; i++) {
        int m = bm + ty * 4 + i;
        float4 v; float* vp = (float*)&v;
        #pragma unroll
        for (int j = 0; j < 4; j++) {
            int n = bn + tx * 4 + j;
            float x = acc[i][j];
            if (bias) x += bias[n];
            if (act)  x = 0.5f * x * (1.f + erff(x * 0.70710678118654752f));
            if (res)  x += res[(size_t)m * N + n];
            vp[j] = x;
        }
        *(float4*)&C[(size_t)m * N + bn + tx * 4] = v;
    }
}

// ---------------- attention scores: S[z] = Q[z] @ K[z]^T * 0.125 ----------------
// z = (s*64+b)*2 + h; Q/K rows stride 384 inside g_QKV.
__global__ void gemm_scores() {
    __shared__ float As[16][64];
    __shared__ float Bs[16][64];
    int z = blockIdx.z;
    int sb = z >> 1, h = z & 1;
    const float* A  = g_QKV + (size_t)sb * NL * 384 + h * 64;          // Q
    const float* Bm = g_QKV + (size_t)sb * NL * 384 + 128 + h * 64;    // K
    float* C = g_S + (size_t)z * NL * NL;
    int tid = threadIdx.x;
    int tx = tid & 15, ty = tid >> 4;
    int bm = blockIdx.y * 64, bn = blockIdx.x * 64;
    int ar = tid >> 2, ac = (tid & 3) * 4;
    float acc[4][4] = {};
    for (int k0 = 0; k0 < 64; k0 += 16) {
        float4 a = *(const float4*)&A[(size_t)(bm + ar) * 384 + k0 + ac];
        As[ac + 0][ar] = a.x; As[ac + 1][ar] = a.y;
        As[ac + 2][ar] = a.z; As[ac + 3][ar] = a.w;
        float4 b = *(const float4*)&Bm[(size_t)(bn + ar) * 384 + k0 + ac];
        Bs[ac + 0][ar] = b.x; Bs[ac + 1][ar] = b.y;
        Bs[ac + 2][ar] = b.z; Bs[ac + 3][ar] = b.w;
        __syncthreads();
        #pragma unroll
        for (int k = 0; k < 16; k++) {
            float av[4], bv[4];
            *(float4*)av = *(float4*)&As[k][ty * 4];
            *(float4*)bv = *(float4*)&Bs[k][tx * 4];
            #pragma unroll
            for (int i = 0; i < 4; i++)
                #pragma unroll
                for (int j = 0; j < 4; j++) acc[i][j] += av[i] * bv[j];
        }
        __syncthreads();
    }
    #pragma unroll
    for (int i = 0; i < 4; i++) {
        int m = bm + ty * 4 + i;
        float4 v; float* vp = (float*)&v;
        #pragma unroll
        for (int j = 0; j < 4; j++) vp[j] = acc[i][j] * 0.125f;
        *(float4*)&C[(size_t)m * NL + bn + tx * 4] = v;
    }
}

// ---------------- softmax over rows of 512 (in-place on g_S) ----------------
__global__ void k_softmax() {
    size_t row = blockIdx.x;
    float* p = g_S + row * NL;
    int t = threadIdx.x;
    float v[4];
    float m = -1e30f;
    #pragma unroll
    for (int i = 0; i < 4; i++) { v[i] = p[t + i * 128]; m = fmaxf(m, v[i]); }
    for (int o = 16; o; o >>= 1) m = fmaxf(m, __shfl_xor_sync(0xffffffffu, m, o));
    __shared__ float sh[4];
    int w = t >> 5;
    if ((t & 31) == 0) sh[w] = m;
    __syncthreads();
    m = fmaxf(fmaxf(sh[0], sh[1]), fmaxf(sh[2], sh[3]));
    __syncthreads();
    float s = 0.f;
    #pragma unroll
    for (int i = 0; i < 4; i++) { v[i] = expf(v[i] - m); s += v[i]; }
    for (int o = 16; o; o >>= 1) s += __shfl_xor_sync(0xffffffffu, s, o);
    if ((t & 31) == 0) sh[w] = s;
    __syncthreads();
    float inv = 1.f / (sh[0] + sh[1] + sh[2] + sh[3]);
    #pragma unroll
    for (int i = 0; i < 4; i++) p[t + i * 128] = v[i] * inv;
}

// ---------------- PV: ctx[z] = P[z] @ V[z] ----------------
__global__ void gemm_pv() {
    __shared__ float As[16][64];
    __shared__ float Bs[16][64];
    int z = blockIdx.z;
    int sb = z >> 1, h = z & 1;
    const float* A  = g_S + (size_t)z * NL * NL;                        // P, lda=512
    const float* Bm = g_QKV + (size_t)sb * NL * 384 + 256 + h * 64;     // V, ldb=384
    float* C = g_CTX + (size_t)sb * NL * ND + h * 64;                   // ldc=128
    int tid = threadIdx.x;
    int tx = tid & 15, ty = tid >> 4;
    int bm = blockIdx.y * 64;                                           // bn = 0 (N=64)
    int ar = tid >> 2, ac = (tid & 3) * 4;
    int br = tid >> 4, bc = (tid & 15) * 4;
    float acc[4][4] = {};
    for (int k0 = 0; k0 < NL; k0 += 16) {
        float4 a = *(const float4*)&A[(size_t)(bm + ar) * NL + k0 + ac];
        As[ac + 0][ar] = a.x; As[ac + 1][ar] = a.y;
        As[ac + 2][ar] = a.z; As[ac + 3][ar] = a.w;
        *(float4*)&Bs[br][bc] = *(const float4*)&Bm[(size_t)(k0 + br) * 384 + bc];
        __syncthreads();
        #pragma unroll
        for (int k = 0; k < 16; k++) {
            float av[4], bv[4];
            *(float4*)av = *(float4*)&As[k][ty * 4];
            *(float4*)bv = *(float4*)&Bs[k][tx * 4];
            #pragma unroll
            for (int i = 0; i < 4; i++)
                #pragma unroll
                for (int j = 0; j < 4; j++) acc[i][j] += av[i] * bv[j];
        }
        __syncthreads();
    }
    #pragma unroll
    for (int i = 0; i < 4; i++) {
        int m = bm + ty * 4 + i;
        float4 v; float* vp = (float*)&v;
        #pragma unroll
        for (int j = 0; j < 4; j++) vp[j] = acc[i][j];
        *(float4*)&C[(size_t)m * ND + tx * 4] = v;
    }
}

// ---------------- launch ----------------
extern "C" void kernel_launch(void* const* d_in, const int* in_sizes, int n_in,
                              void* d_out, int out_size) {
    const int*   src    = (const int*)d_in[0];
    const int*   dst    = (const int*)d_in[1];
    const float* w1     = (const float*)d_in[2];
    const float* b1     = (const float*)d_in[3];
    const float* w2     = (const float*)d_in[4];
    const float* b2     = (const float*)d_in[5];
    const float* proj_w = (const float*)d_in[6];
    const float* proj_b = (const float*)d_in[7];
    const float* ln1_g  = (const float*)d_in[8];
    const float* ln1_b  = (const float*)d_in[9];
    const float* w_qkv  = (const float*)d_in[10];
    const float* b_qkv  = (const float*)d_in[11];
    const float* w_o    = (const float*)d_in[12];
    const float* b_o    = (const float*)d_in[13];
    const float* ln2_g  = (const float*)d_in[14];
    const float* ln2_b  = (const float*)d_in[15];
    const float* w_ff1  = (const float*)d_in[16];
    const float* b_ff1  = (const float*)d_in[17];
    const float* w_ff2  = (const float*)d_in[18];
    const float* b_ff2  = (const float*)d_in[19];
    float* out = (float*)d_out;

    // precompute fused encode+proj table
    k_W    <<<ND, ND>>>(w2, proj_w);
    k_bias <<<1, ND>>>(b2, proj_w, proj_b);
    k_table<<<513, ND>>>(w1, b1);

    // co-occurrence counts + feature build (both streams)
    k_cooc<<<NB, NL>>>(src, dst);
    k_feat<<<(NTOK * ND) / 256, 256>>>();

    // transformer (both streams batched: 65536 tokens)
    k_ln<<<NTOK, ND>>>(BUF_X, BUF_H, ln1_g, ln1_b);
    gemm_nn<<<dim3(6, NTOK / 64), 256>>>(BUF_H, w_qkv, b_qkv, -1, BUF_QKV, nullptr,
                                         NTOK, 384, 128, 0);
    gemm_scores<<<dim3(8, 8, NHB), 256>>>();
    k_softmax<<<NHB * NL, 128>>>();
    gemm_pv<<<dim3(1, 8, NHB), 256>>>();
    gemm_nn<<<dim3(2, NTOK / 64), 256>>>(BUF_CTX, w_o, b_o, BUF_X, BUF_X, nullptr,
                                         NTOK, 128, 128, 0);
    k_ln<<<NTOK, ND>>>(BUF_X, BUF_H, ln2_g, ln2_b);
    gemm_nn<<<dim3(8, NTOK / 64), 256>>>(BUF_H, w_ff1, b_ff1, -1, BUF_FF, nullptr,
                                         NTOK, 512, 128, 1);
    gemm_nn<<<dim3(2, NTOK / 64), 256>>>(BUF_FF, w_ff2, b_ff2, BUF_X, BUF_X, out,
                                         NTOK, 128, 512, 0);
}

// round 4
// speedup vs baseline: 1.6862x; 1.6862x over previous
#include <cuda_runtime.h>
#include <math.h>

#define NB    64
#define NL    512
#define ND    128
#define TOKS  32768          // B*L per stream
#define NTOK  65536          // 2*B*L
#define NHB   256            // 2*B*H attention batches

// ---------------- scratch (device globals; no allocation allowed) ----------------
__device__ int   g_cnt[NTOK * 2];
__device__ float g_W[ND * ND];
__device__ float g_biasT[ND];
__device__ float g_T2[513 * ND];
__device__ float g_X[(size_t)NTOK * ND];
__device__ float g_H[(size_t)NTOK * ND];
__device__ float g_QKV[(size_t)NTOK * 3 * ND];
__device__ float g_S[(size_t)NHB * NL * NL];
__device__ float g_CTX[(size_t)NTOK * ND];
__device__ float g_FF[(size_t)NTOK * 4 * ND];

#define BUF_X    0
#define BUF_H    1
#define BUF_QKV  2
#define BUF_CTX  3
#define BUF_FF   4
__device__ __forceinline__ float* buf(int id) {
    switch (id) {
        case BUF_X:   return g_X;
        case BUF_H:   return g_H;
        case BUF_QKV: return g_QKV;
        case BUF_CTX: return g_CTX;
        default:      return g_FF;
    }
}

// fp32 -> tf32 (round to nearest)
__device__ __forceinline__ float f2tf(float x) {
    unsigned r;
    asm("cvt.rna.tf32.f32 %0, %1;" : "=r"(r) : "f"(x));
    return __uint_as_float(r);
}

__device__ __forceinline__ void mma_tf32(float* c, const unsigned* a, const unsigned* b) {
    asm volatile(
        "mma.sync.aligned.m16n8k8.row.col.f32.tf32.tf32.f32 "
        "{%0,%1,%2,%3}, {%4,%5,%6,%7}, {%8,%9}, {%0,%1,%2,%3};"
        : "+f"(c[0]), "+f"(c[1]), "+f"(c[2]), "+f"(c[3])
        : "r"(a[0]), "r"(a[1]), "r"(a[2]), "r"(a[3]), "r"(b[0]), "r"(b[1]));
}

// ---------------- tiny precompute kernels ----------------
__global__ void k_W(const float* __restrict__ w2, const float* __restrict__ proj_w) {
    int k = blockIdx.x, d = threadIdx.x;
    float acc = 0.f;
    #pragma unroll 8
    for (int j = 0; j < ND; j++) acc += w2[k * ND + j] * proj_w[j * ND + d];
    g_W[k * ND + d] = acc;
}

__global__ void k_bias(const float* __restrict__ b2, const float* __restrict__ proj_w,
                       const float* __restrict__ proj_b) {
    int d = threadIdx.x;
    float acc = proj_b[d];
    #pragma unroll 8
    for (int k = 0; k < ND; k++) acc += 2.f * b2[k] * proj_w[k * ND + d];
    g_biasT[d] = acc;
}

__global__ void k_table(const float* __restrict__ w1, const float* __restrict__ b1) {
    __shared__ float h[ND];
    int c = blockIdx.x, d = threadIdx.x;
    h[d] = fmaxf((float)c * w1[d] + b1[d], 0.f);
    __syncthreads();
    float acc = 0.5f * g_biasT[d];
    #pragma unroll 8
    for (int k = 0; k < ND; k++) acc += h[k] * g_W[k * ND + d];
    g_T2[c * ND + d] = acc;
}

// ---------------- co-occurrence counts ----------------
__global__ void k_cooc(const int* __restrict__ src, const int* __restrict__ dst) {
    __shared__ int ss[NL], dd[NL];
    int b = blockIdx.x, i = threadIdx.x;
    ss[i] = src[b * NL + i];
    dd[i] = dst[b * NL + i];
    __syncthreads();
    int qs = ss[i], qd = dd[i];
    int css = 0, csd = 0, cds = 0, cdd = 0;
    #pragma unroll 8
    for (int j = 0; j < NL; j++) {
        int s = ss[j], t = dd[j];
        css += (qs == s); csd += (qs == t);
        cds += (qd == s); cdd += (qd == t);
    }
    if (qs == 0) { css = 0; csd = 0; }
    if (qd == 0) { cds = 0; cdd = 0; }
    int ts = b * NL + i, td = TOKS + b * NL + i;
    g_cnt[ts * 2 + 0] = css; g_cnt[ts * 2 + 1] = csd;
    g_cnt[td * 2 + 0] = cds; g_cnt[td * 2 + 1] = cdd;
}

__global__ void k_feat() {
    int idx = blockIdx.x * 256 + threadIdx.x;
    int t = idx >> 7, d = idx & 127;
    int c0 = g_cnt[t * 2], c1 = g_cnt[t * 2 + 1];
    g_X[idx] = g_T2[c0 * ND + d] + g_T2[c1 * ND + d];
}

// ---------------- layernorm ----------------
__global__ void k_ln(int xid, int yid,
                     const float* __restrict__ g, const float* __restrict__ b) {
    const float* x = buf(xid);
    float* y = buf(yid);
    int row = blockIdx.x, t = threadIdx.x;
    float v = x[(size_t)row * ND + t];
    __shared__ float sh[4];
    float s = v;
    for (int o = 16; o; o >>= 1) s += __shfl_xor_sync(0xffffffffu, s, o);
    int w = t >> 5;
    if ((t & 31) == 0) sh[w] = s;
    __syncthreads();
    float mu = (sh[0] + sh[1] + sh[2] + sh[3]) * (1.f / 128.f);
    __syncthreads();
    float dlt = v - mu;
    float s2 = dlt * dlt;
    for (int o = 16; o; o >>= 1) s2 += __shfl_xor_sync(0xffffffffu, s2, o);
    if ((t & 31) == 0) sh[w] = s2;
    __syncthreads();
    float var = (sh[0] + sh[1] + sh[2] + sh[3]) * (1.f / 128.f);
    float r = rsqrtf(var + 1e-5f);
    y[(size_t)row * ND + t] = dlt * r * g[t] + b[t];
}

// ============ tf32 tensor-core GEMM: C = act(A@B + bias) + res ============
// Block tile 128x64, BK=16, 256 threads = 8 warps (4 M x 2 N), warp tile 32x32.
// A: MxK row-major (lda=K), B: KxN row-major (ldb=N), C/res: MxN (ldc=N).
#define APITCH 132
#define BPITCH 68
__global__ void gemm_tf32(int Aid, const float* __restrict__ Bm,
                          const float* __restrict__ bias, int resid,
                          int Cid, float* __restrict__ cext,
                          int M, int N, int K, int act) {
    const float* A = buf(Aid);
    const float* res = (resid >= 0) ? buf(resid) : nullptr;
    float* C = cext ? cext : buf(Cid);
    __shared__ float As[16][APITCH];
    __shared__ float Bs[16][BPITCH];
    int tid = threadIdx.x;
    int lane = tid & 31, warp = tid >> 5;
    int wm = (warp >> 1) * 32, wn = (warp & 1) * 32;
    int gid = lane >> 2, tig = lane & 3;
    int bm = blockIdx.y * 128, bn = blockIdx.x * 64;

    int m_ = tid >> 2, ac = (tid & 3) * 4;
    int kb = tid >> 4, nb = (tid & 15) * 4;

    float acc[2][4][4] = {};
    for (int k0 = 0; k0 < K; k0 += 16) {
        float4 av0 = *(const float4*)&A[(size_t)(bm + m_) * K + k0 + ac];
        float4 av1 = *(const float4*)&A[(size_t)(bm + m_ + 64) * K + k0 + ac];
        As[ac + 0][m_] = f2tf(av0.x); As[ac + 1][m_] = f2tf(av0.y);
        As[ac + 2][m_] = f2tf(av0.z); As[ac + 3][m_] = f2tf(av0.w);
        As[ac + 0][m_ + 64] = f2tf(av1.x); As[ac + 1][m_ + 64] = f2tf(av1.y);
        As[ac + 2][m_ + 64] = f2tf(av1.z); As[ac + 3][m_ + 64] = f2tf(av1.w);
        float4 bv = *(const float4*)&Bm[(size_t)(k0 + kb) * N + bn + nb];
        Bs[kb][nb + 0] = f2tf(bv.x); Bs[kb][nb + 1] = f2tf(bv.y);
        Bs[kb][nb + 2] = f2tf(bv.z); Bs[kb][nb + 3] = f2tf(bv.w);
        __syncthreads();
        #pragma unroll
        for (int kk = 0; kk < 16; kk += 8) {
            unsigned af[2][4], bf[4][2];
            #pragma unroll
            for (int mi = 0; mi < 2; mi++) {
                int mb = wm + mi * 16 + gid;
                af[mi][0] = __float_as_uint(As[kk + tig][mb]);
                af[mi][1] = __float_as_uint(As[kk + tig][mb + 8]);
                af[mi][2] = __float_as_uint(As[kk + tig + 4][mb]);
                af[mi][3] = __float_as_uint(As[kk + tig + 4][mb + 8]);
            }
            #pragma unroll
            for (int ni = 0; ni < 4; ni++) {
                int nbb = wn + ni * 8 + gid;
                bf[ni][0] = __float_as_uint(Bs[kk + tig][nbb]);
                bf[ni][1] = __float_as_uint(Bs[kk + tig + 4][nbb]);
            }
            #pragma unroll
            for (int mi = 0; mi < 2; mi++)
                #pragma unroll
                for (int ni = 0; ni < 4; ni++)
                    mma_tf32(acc[mi][ni], af[mi], bf[ni]);
        }
        __syncthreads();
    }
    #pragma unroll
    for (int mi = 0; mi < 2; mi++) {
        int r0 = bm + wm + mi * 16 + gid;
        #pragma unroll
        for (int ni = 0; ni < 4; ni++) {
            int col = bn + wn + ni * 8 + tig * 2;
            float x0 = acc[mi][ni][0], x1 = acc[mi][ni][1];
            float x2 = acc[mi][ni][2], x3 = acc[mi][ni][3];
            if (bias) {
                float bb0 = bias[col], bb1 = bias[col + 1];
                x0 += bb0; x1 += bb1; x2 += bb0; x3 += bb1;
            }
            if (act) {
                x0 = 0.5f * x0 * (1.f + erff(x0 * 0.70710678118654752f));
                x1 = 0.5f * x1 * (1.f + erff(x1 * 0.70710678118654752f));
                x2 = 0.5f * x2 * (1.f + erff(x2 * 0.70710678118654752f));
                x3 = 0.5f * x3 * (1.f + erff(x3 * 0.70710678118654752f));
            }
            if (res) {
                x0 += res[(size_t)r0 * N + col];     x1 += res[(size_t)r0 * N + col + 1];
                x2 += res[(size_t)(r0 + 8) * N + col]; x3 += res[(size_t)(r0 + 8) * N + col + 1];
            }
            *(float2*)&C[(size_t)r0 * N + col] = make_float2(x0, x1);
            *(float2*)&C[(size_t)(r0 + 8) * N + col] = make_float2(x2, x3);
        }
    }
}

// ============ scores: S[z] = Q[z] @ K[z]^T * 0.125 (tf32 mma) ============
// z = blockIdx.z; Q rows lda=384; K rows (as B^T) loaded along k.
__global__ void scores_tf32() {
    __shared__ float As[16][APITCH];
    __shared__ float Bs[16][BPITCH];
    int z = blockIdx.z;
    int sb = z >> 1, h = z & 1;
    const float* Aq = g_QKV + (size_t)sb * NL * 384 + h * 64;
    const float* Kp = g_QKV + (size_t)sb * NL * 384 + 128 + h * 64;
    float* C = g_S + (size_t)z * NL * NL;
    int tid = threadIdx.x;
    int lane = tid & 31, warp = tid >> 5;
    int wm = (warp >> 1) * 32, wn = (warp & 1) * 32;
    int gid = lane >> 2, tig = lane & 3;
    int bm = blockIdx.y * 128, bn = blockIdx.x * 64;

    int m_ = tid >> 2, ac = (tid & 3) * 4;

    float acc[2][4][4] = {};
    for (int k0 = 0; k0 < 64; k0 += 16) {
        float4 av0 = *(const float4*)&Aq[(size_t)(bm + m_) * 384 + k0 + ac];
        float4 av1 = *(const float4*)&Aq[(size_t)(bm + m_ + 64) * 384 + k0 + ac];
        As[ac + 0][m_] = f2tf(av0.x); As[ac + 1][m_] = f2tf(av0.y);
        As[ac + 2][m_] = f2tf(av0.z); As[ac + 3][m_] = f2tf(av0.w);
        As[ac + 0][m_ + 64] = f2tf(av1.x); As[ac + 1][m_ + 64] = f2tf(av1.y);
        As[ac + 2][m_ + 64] = f2tf(av1.z); As[ac + 3][m_ + 64] = f2tf(av1.w);
        float4 bv = *(const float4*)&Kp[(size_t)(bn + m_) * 384 + k0 + ac];
        Bs[ac + 0][m_] = f2tf(bv.x); Bs[ac + 1][m_] = f2tf(bv.y);
        Bs[ac + 2][m_] = f2tf(bv.z); Bs[ac + 3][m_] = f2tf(bv.w);
        __syncthreads();
        #pragma unroll
        for (int kk = 0; kk < 16; kk += 8) {
            unsigned af[2][4], bf[4][2];
            #pragma unroll
            for (int mi = 0; mi < 2; mi++) {
                int mb = wm + mi * 16 + gid;
                af[mi][0] = __float_as_uint(As[kk + tig][mb]);
                af[mi][1] = __float_as_uint(As[kk + tig][mb + 8]);
                af[mi][2] = __float_as_uint(As[kk + tig + 4][mb]);
                af[mi][3] = __float_as_uint(As[kk + tig + 4][mb + 8]);
            }
            #pragma unroll
            for (int ni = 0; ni < 4; ni++) {
                int nbb = wn + ni * 8 + gid;
                bf[ni][0] = __float_as_uint(Bs[kk + tig][nbb]);
                bf[ni][1] = __float_as_uint(Bs[kk + tig + 4][nbb]);
            }
            #pragma unroll
            for (int mi = 0; mi < 2; mi++)
                #pragma unroll
                for (int ni = 0; ni < 4; ni++)
                    mma_tf32(acc[mi][ni], af[mi], bf[ni]);
        }
        __syncthreads();
    }
    #pragma unroll
    for (int mi = 0; mi < 2; mi++) {
        int r0 = bm + wm + mi * 16 + gid;
        #pragma unroll
        for (int ni = 0; ni < 4; ni++) {
            int col = bn + wn + ni * 8 + tig * 2;
            *(float2*)&C[(size_t)r0 * NL + col] =
                make_float2(acc[mi][ni][0] * 0.125f, acc[mi][ni][1] * 0.125f);
            *(float2*)&C[(size_t)(r0 + 8) * NL + col] =
                make_float2(acc[mi][ni][2] * 0.125f, acc[mi][ni][3] * 0.125f);
        }
    }
}

// ---------------- softmax over rows of 512 (in-place on g_S) ----------------
__global__ void k_softmax() {
    size_t row = blockIdx.x;
    float* p = g_S + row * NL;
    int t = threadIdx.x;
    float v[4];
    float m = -1e30f;
    #pragma unroll
    for (int i = 0; i < 4; i++) { v[i] = p[t + i * 128]; m = fmaxf(m, v[i]); }
    for (int o = 16; o; o >>= 1) m = fmaxf(m, __shfl_xor_sync(0xffffffffu, m, o));
    __shared__ float sh[4];
    int w = t >> 5;
    if ((t & 31) == 0) sh[w] = m;
    __syncthreads();
    m = fmaxf(fmaxf(sh[0], sh[1]), fmaxf(sh[2], sh[3]));
    __syncthreads();
    float s = 0.f;
    #pragma unroll
    for (int i = 0; i < 4; i++) { v[i] = expf(v[i] - m); s += v[i]; }
    for (int o = 16; o; o >>= 1) s += __shfl_xor_sync(0xffffffffu, s, o);
    if ((t & 31) == 0) sh[w] = s;
    __syncthreads();
    float inv = 1.f / (sh[0] + sh[1] + sh[2] + sh[3]);
    #pragma unroll
    for (int i = 0; i < 4; i++) p[t + i * 128] = v[i] * inv;
}

// ============ PV: ctx[z] = P[z] @ V[z] (tf32 mma) ============
__global__ void pv_tf32() {
    __shared__ float As[16][APITCH];
    __shared__ float Bs[16][BPITCH];
    int z = blockIdx.z;
    int sb = z >> 1, h = z & 1;
    const float* A  = g_S + (size_t)z * NL * NL;                    // 512x512
    const float* Vp = g_QKV + (size_t)sb * NL * 384 + 256 + h * 64; // ldb=384
    float* C = g_CTX + (size_t)sb * NL * ND + h * 64;               // ldc=128
    int tid = threadIdx.x;
    int lane = tid & 31, warp = tid >> 5;
    int wm = (warp >> 1) * 32, wn = (warp & 1) * 32;
    int gid = lane >> 2, tig = lane & 3;
    int bm = blockIdx.y * 128;

    int m_ = tid >> 2, ac = (tid & 3) * 4;
    int kb = tid >> 4, nb = (tid & 15) * 4;

    float acc[2][4][4] = {};
    for (int k0 = 0; k0 < NL; k0 += 16) {
        float4 av0 = *(const float4*)&A[(size_t)(bm + m_) * NL + k0 + ac];
        float4 av1 = *(const float4*)&A[(size_t)(bm + m_ + 64) * NL + k0 + ac];
        As[ac + 0][m_] = f2tf(av0.x); As[ac + 1][m_] = f2tf(av0.y);
        As[ac + 2][m_] = f2tf(av0.z); As[ac + 3][m_] = f2tf(av0.w);
        As[ac + 0][m_ + 64] = f2tf(av1.x); As[ac + 1][m_ + 64] = f2tf(av1.y);
        As[ac + 2][m_ + 64] = f2tf(av1.z); As[ac + 3][m_ + 64] = f2tf(av1.w);
        float4 bv = *(const float4*)&Vp[(size_t)(k0 + kb) * 384 + nb];
        Bs[kb][nb + 0] = f2tf(bv.x); Bs[kb][nb + 1] = f2tf(bv.y);
        Bs[kb][nb + 2] = f2tf(bv.z); Bs[kb][nb + 3] = f2tf(bv.w);
        __syncthreads();
        #pragma unroll
        for (int kk = 0; kk < 16; kk += 8) {
            unsigned af[2][4], bf[4][2];
            #pragma unroll
            for (int mi = 0; mi < 2; mi++) {
                int mb = wm + mi * 16 + gid;
                af[mi][0] = __float_as_uint(As[kk + tig][mb]);
                af[mi][1] = __float_as_uint(As[kk + tig][mb + 8]);
                af[mi][2] = __float_as_uint(As[kk + tig + 4][mb]);
                af[mi][3] = __float_as_uint(As[kk + tig + 4][mb + 8]);
            }
            #pragma unroll
            for (int ni = 0; ni < 4; ni++) {
                int nbb = wn + ni * 8 + gid;
                bf[ni][0] = __float_as_uint(Bs[kk + tig][nbb]);
                bf[ni][1] = __float_as_uint(Bs[kk + tig + 4][nbb]);
            }
            #pragma unroll
            for (int mi = 0; mi < 2; mi++)
                #pragma unroll
                for (int ni = 0; ni < 4; ni++)
                    mma_tf32(acc[mi][ni], af[mi], bf[ni]);
        }
        __syncthreads();
    }
    #pragma unroll
    for (int mi = 0; mi < 2; mi++) {
        int r0 = bm + wm + mi * 16 + gid;
        #pragma unroll
        for (int ni = 0; ni < 4; ni++) {
            int col = wn + ni * 8 + tig * 2;
            *(float2*)&C[(size_t)r0 * ND + col] =
                make_float2(acc[mi][ni][0], acc[mi][ni][1]);
            *(float2*)&C[(size_t)(r0 + 8) * ND + col] =
                make_float2(acc[mi][ni][2], acc[mi][ni][3]);
        }
    }
}

// ---------------- launch ----------------
extern "C" void kernel_launch(void* const* d_in, const int* in_sizes, int n_in,
                              void* d_out, int out_size) {
    const int*   src    = (const int*)d_in[0];
    const int*   dst    = (const int*)d_in[1];
    const float* w1     = (const float*)d_in[2];
    const float* b1     = (const float*)d_in[3];
    const float* w2     = (const float*)d_in[4];
    const float* b2     = (const float*)d_in[5];
    const float* proj_w = (const float*)d_in[6];
    const float* proj_b = (const float*)d_in[7];
    const float* ln1_g  = (const float*)d_in[8];
    const float* ln1_b  = (const float*)d_in[9];
    const float* w_qkv  = (const float*)d_in[10];
    const float* b_qkv  = (const float*)d_in[11];
    const float* w_o    = (const float*)d_in[12];
    const float* b_o    = (const float*)d_in[13];
    const float* ln2_g  = (const float*)d_in[14];
    const float* ln2_b  = (const float*)d_in[15];
    const float* w_ff1  = (const float*)d_in[16];
    const float* b_ff1  = (const float*)d_in[17];
    const float* w_ff2  = (const float*)d_in[18];
    const float* b_ff2  = (const float*)d_in[19];
    float* out = (float*)d_out;

    // precompute fused encode+proj table
    k_W    <<<ND, ND>>>(w2, proj_w);
    k_bias <<<1, ND>>>(b2, proj_w, proj_b);
    k_table<<<513, ND>>>(w1, b1);

    // co-occurrence counts + feature build (both streams)
    k_cooc<<<NB, NL>>>(src, dst);
    k_feat<<<(NTOK * ND) / 256, 256>>>();

    // transformer (both streams batched: 65536 tokens)
    k_ln<<<NTOK, ND>>>(BUF_X, BUF_H, ln1_g, ln1_b);
    gemm_tf32<<<dim3(6, NTOK / 128), 256>>>(BUF_H, w_qkv, b_qkv, -1, BUF_QKV, nullptr,
                                            NTOK, 384, 128, 0);
    scores_tf32<<<dim3(8, 4, NHB), 256>>>();
    k_softmax<<<NHB * NL, 128>>>();
    pv_tf32<<<dim3(1, 4, NHB), 256>>>();
    gemm_tf32<<<dim3(2, NTOK / 128), 256>>>(BUF_CTX, w_o, b_o, BUF_X, BUF_X, nullptr,
                                            NTOK, 128, 128, 0);
    k_ln<<<NTOK, ND>>>(BUF_X, BUF_H, ln2_g, ln2_b);
    gemm_tf32<<<dim3(8, NTOK / 128), 256>>>(BUF_H, w_ff1, b_ff1, -1, BUF_FF, nullptr,
                                            NTOK, 512, 128, 1);
    gemm_tf32<<<dim3(2, NTOK / 128), 256>>>(BUF_FF, w_ff2, b_ff2, BUF_X, BUF_X, out,
                                            NTOK, 128, 512, 0);
}

// round 6
// speedup vs baseline: 1.8312x; 1.0859x over previous
#include <cuda_runtime.h>
#include <math.h>

#define NB    64
#define NL    512
#define ND    128
#define TOKS  32768          // B*L per stream
#define NTOK  65536          // 2*B*L
#define NHB   256            // 2*B*H attention batches

// ---------------- scratch (device globals; no allocation allowed) ----------------
__device__ int   g_cnt[NTOK * 2];
__device__ float g_W[ND * ND];
__device__ float g_biasT[ND];
__device__ float g_T2[513 * ND];
__device__ float g_X[(size_t)NTOK * ND];
__device__ float g_H[(size_t)NTOK * ND];
__device__ float g_QKV[(size_t)NTOK * 3 * ND];
__device__ float g_CTX[(size_t)NTOK * ND];
__device__ float g_FF[(size_t)NTOK * 4 * ND];

#define BUF_X    0
#define BUF_H    1
#define BUF_QKV  2
#define BUF_CTX  3
#define BUF_FF   4
__device__ __forceinline__ float* buf(int id) {
    switch (id) {
        case BUF_X:   return g_X;
        case BUF_H:   return g_H;
        case BUF_QKV: return g_QKV;
        case BUF_CTX: return g_CTX;
        default:      return g_FF;
    }
}

// fp32 -> tf32 (round to nearest)
__device__ __forceinline__ float f2tf(float x) {
    unsigned r;
    asm("cvt.rna.tf32.f32 %0, %1;" : "=r"(r) : "f"(x));
    return __uint_as_float(r);
}

__device__ __forceinline__ void mma_tf32(float* c, const unsigned* a, const unsigned* b) {
    asm volatile(
        "mma.sync.aligned.m16n8k8.row.col.f32.tf32.tf32.f32 "
        "{%0,%1,%2,%3}, {%4,%5,%6,%7}, {%8,%9}, {%0,%1,%2,%3};"
        : "+f"(c[0]), "+f"(c[1]), "+f"(c[2]), "+f"(c[3])
        : "r"(a[0]), "r"(a[1]), "r"(a[2]), "r"(a[3]), "r"(b[0]), "r"(b[1]));
}

// ---------------- tiny precompute kernels ----------------
__global__ void k_W(const float* __restrict__ w2, const float* __restrict__ proj_w) {
    int k = blockIdx.x, d = threadIdx.x;
    float acc = 0.f;
    #pragma unroll 8
    for (int j = 0; j < ND; j++) acc += w2[k * ND + j] * proj_w[j * ND + d];
    g_W[k * ND + d] = acc;
}

__global__ void k_bias(const float* __restrict__ b2, const float* __restrict__ proj_w,
                       const float* __restrict__ proj_b) {
    int d = threadIdx.x;
    float acc = proj_b[d];
    #pragma unroll 8
    for (int k = 0; k < ND; k++) acc += 2.f * b2[k] * proj_w[k * ND + d];
    g_biasT[d] = acc;
}

__global__ void k_table(const float* __restrict__ w1, const float* __restrict__ b1) {
    __shared__ float h[ND];
    int c = blockIdx.x, d = threadIdx.x;
    h[d] = fmaxf((float)c * w1[d] + b1[d], 0.f);
    __syncthreads();
    float acc = 0.5f * g_biasT[d];
    #pragma unroll 8
    for (int k = 0; k < ND; k++) acc += h[k] * g_W[k * ND + d];
    g_T2[c * ND + d] = acc;
}

// ---------------- co-occurrence counts ----------------
__global__ void k_cooc(const int* __restrict__ src, const int* __restrict__ dst) {
    __shared__ int ss[NL], dd[NL];
    int b = blockIdx.x, i = threadIdx.x;
    ss[i] = src[b * NL + i];
    dd[i] = dst[b * NL + i];
    __syncthreads();
    int qs = ss[i], qd = dd[i];
    int css = 0, csd = 0, cds = 0, cdd = 0;
    #pragma unroll 8
    for (int j = 0; j < NL; j++) {
        int s = ss[j], t = dd[j];
        css += (qs == s); csd += (qs == t);
        cds += (qd == s); cdd += (qd == t);
    }
    if (qs == 0) { css = 0; csd = 0; }
    if (qd == 0) { cds = 0; cdd = 0; }
    int ts = b * NL + i, td = TOKS + b * NL + i;
    g_cnt[ts * 2 + 0] = css; g_cnt[ts * 2 + 1] = csd;
    g_cnt[td * 2 + 0] = cds; g_cnt[td * 2 + 1] = cdd;
}

__global__ void k_feat() {
    int idx = blockIdx.x * 256 + threadIdx.x;
    int t = idx >> 7, d = idx & 127;
    int c0 = g_cnt[t * 2], c1 = g_cnt[t * 2 + 1];
    g_X[idx] = g_T2[c0 * ND + d] + g_T2[c1 * ND + d];
}

// ---------------- layernorm ----------------
__global__ void k_ln(int xid, int yid,
                     const float* __restrict__ g, const float* __restrict__ b) {
    const float* x = buf(xid);
    float* y = buf(yid);
    int row = blockIdx.x, t = threadIdx.x;
    float v = x[(size_t)row * ND + t];
    __shared__ float sh[4];
    float s = v;
    for (int o = 16; o; o >>= 1) s += __shfl_xor_sync(0xffffffffu, s, o);
    int w = t >> 5;
    if ((t & 31) == 0) sh[w] = s;
    __syncthreads();
    float mu = (sh[0] + sh[1] + sh[2] + sh[3]) * (1.f / 128.f);
    __syncthreads();
    float dlt = v - mu;
    float s2 = dlt * dlt;
    for (int o = 16; o; o >>= 1) s2 += __shfl_xor_sync(0xffffffffu, s2, o);
    if ((t & 31) == 0) sh[w] = s2;
    __syncthreads();
    float var = (sh[0] + sh[1] + sh[2] + sh[3]) * (1.f / 128.f);
    float r = rsqrtf(var + 1e-5f);
    y[(size_t)row * ND + t] = dlt * r * g[t] + b[t];
}

// ============ tf32 tensor-core GEMM: C = act(A@B + bias) + res ============
#define APITCH 132
#define BPITCH 68
__global__ void gemm_tf32(int Aid, const float* __restrict__ Bm,
                          const float* __restrict__ bias, int resid,
                          int Cid, float* __restrict__ cext,
                          int M, int N, int K, int act) {
    const float* A = buf(Aid);
    const float* res = (resid >= 0) ? buf(resid) : nullptr;
    float* C = cext ? cext : buf(Cid);
    __shared__ float As[16][APITCH];
    __shared__ float Bs[16][BPITCH];
    int tid = threadIdx.x;
    int lane = tid & 31, warp = tid >> 5;
    int wm = (warp >> 1) * 32, wn = (warp & 1) * 32;
    int gid = lane >> 2, tig = lane & 3;
    int bm = blockIdx.y * 128, bn = blockIdx.x * 64;

    int m_ = tid >> 2, ac = (tid & 3) * 4;
    int kb = tid >> 4, nb = (tid & 15) * 4;

    float acc[2][4][4] = {};
    for (int k0 = 0; k0 < K; k0 += 16) {
        float4 av0 = *(const float4*)&A[(size_t)(bm + m_) * K + k0 + ac];
        float4 av1 = *(const float4*)&A[(size_t)(bm + m_ + 64) * K + k0 + ac];
        As[ac + 0][m_] = f2tf(av0.x); As[ac + 1][m_] = f2tf(av0.y);
        As[ac + 2][m_] = f2tf(av0.z); As[ac + 3][m_] = f2tf(av0.w);
        As[ac + 0][m_ + 64] = f2tf(av1.x); As[ac + 1][m_ + 64] = f2tf(av1.y);
        As[ac + 2][m_ + 64] = f2tf(av1.z); As[ac + 3][m_ + 64] = f2tf(av1.w);
        float4 bv = *(const float4*)&Bm[(size_t)(k0 + kb) * N + bn + nb];
        Bs[kb][nb + 0] = f2tf(bv.x); Bs[kb][nb + 1] = f2tf(bv.y);
        Bs[kb][nb + 2] = f2tf(bv.z); Bs[kb][nb + 3] = f2tf(bv.w);
        __syncthreads();
        #pragma unroll
        for (int kk = 0; kk < 16; kk += 8) {
            unsigned af[2][4], bf[4][2];
            #pragma unroll
            for (int mi = 0; mi < 2; mi++) {
                int mb = wm + mi * 16 + gid;
                af[mi][0] = __float_as_uint(As[kk + tig][mb]);
                af[mi][1] = __float_as_uint(As[kk + tig][mb + 8]);
                af[mi][2] = __float_as_uint(As[kk + tig + 4][mb]);
                af[mi][3] = __float_as_uint(As[kk + tig + 4][mb + 8]);
            }
            #pragma unroll
            for (int ni = 0; ni < 4; ni++) {
                int nbb = wn + ni * 8 + gid;
                bf[ni][0] = __float_as_uint(Bs[kk + tig][nbb]);
                bf[ni][1] = __float_as_uint(Bs[kk + tig + 4][nbb]);
            }
            #pragma unroll
            for (int mi = 0; mi < 2; mi++)
                #pragma unroll
                for (int ni = 0; ni < 4; ni++)
                    mma_tf32(acc[mi][ni], af[mi], bf[ni]);
        }
        __syncthreads();
    }
    #pragma unroll
    for (int mi = 0; mi < 2; mi++) {
        int r0 = bm + wm + mi * 16 + gid;
        #pragma unroll
        for (int ni = 0; ni < 4; ni++) {
            int col = bn + wn + ni * 8 + tig * 2;
            float x0 = acc[mi][ni][0], x1 = acc[mi][ni][1];
            float x2 = acc[mi][ni][2], x3 = acc[mi][ni][3];
            if (bias) {
                float bb0 = bias[col], bb1 = bias[col + 1];
                x0 += bb0; x1 += bb1; x2 += bb0; x3 += bb1;
            }
            if (act) {
                x0 = 0.5f * x0 * (1.f + erff(x0 * 0.70710678118654752f));
                x1 = 0.5f * x1 * (1.f + erff(x1 * 0.70710678118654752f));
                x2 = 0.5f * x2 * (1.f + erff(x2 * 0.70710678118654752f));
                x3 = 0.5f * x3 * (1.f + erff(x3 * 0.70710678118654752f));
            }
            if (res) {
                x0 += res[(size_t)r0 * N + col];     x1 += res[(size_t)r0 * N + col + 1];
                x2 += res[(size_t)(r0 + 8) * N + col]; x3 += res[(size_t)(r0 + 8) * N + col + 1];
            }
            *(float2*)&C[(size_t)r0 * N + col] = make_float2(x0, x1);
            *(float2*)&C[(size_t)(r0 + 8) * N + col] = make_float2(x2, x3);
        }
    }
}

// ============ fused flash attention (tf32): ctx = softmax(Q K^T / 8) V ============
// Grid: (NL/128, NHB). CTA: 256 threads = 8 warps, EACH WARP OWNS 16 FULL ROWS
// (warp m-tile 16, n covers all 128 keys) so softmax stats never cross warps.
#define QPITCH 132
#define VPITCH 68
#define SM_Q   0
#define SM_K   (64 * QPITCH)
#define SM_V   (SM_K + 64 * QPITCH)
#define SM_P   (SM_V + 128 * VPITCH)
#define SM_TOT ((SM_P + 128 * QPITCH) * 4)

__global__ __launch_bounds__(256, 1) void flash_tf32() {
    extern __shared__ float sm[];
    float* Qs = sm + SM_Q;
    float* Ks = sm + SM_K;
    float* Vs = sm + SM_V;
    float* Ps = sm + SM_P;

    int z = blockIdx.y;
    int sb = z >> 1, h = z & 1;
    const float* Qp = g_QKV + (size_t)sb * NL * 384 + h * 64;
    const float* Kp = Qp + 128;
    const float* Vp = Qp + 256;
    float* Cp = g_CTX + (size_t)sb * NL * ND + h * 64;

    int bm = blockIdx.x * 128;
    int tid = threadIdx.x, lane = tid & 31, warp = tid >> 5;
    int wm = warp * 16;           // each warp: rows wm..wm+15
    int gid = lane >> 2, tig = lane & 3;

    // ---- load Q tile (transposed, tf32, pre-scaled by 1/sqrt(64)) ----
    {
        int qm = tid & 127, qk = (tid >> 7) * 32;
        #pragma unroll
        for (int i = 0; i < 8; i++) {
            float4 v = *(const float4*)&Qp[(size_t)(bm + qm) * 384 + qk + i * 4];
            Qs[(qk + i * 4 + 0) * QPITCH + qm] = f2tf(v.x * 0.125f);
            Qs[(qk + i * 4 + 1) * QPITCH + qm] = f2tf(v.y * 0.125f);
            Qs[(qk + i * 4 + 2) * QPITCH + qm] = f2tf(v.z * 0.125f);
            Qs[(qk + i * 4 + 3) * QPITCH + qm] = f2tf(v.w * 0.125f);
        }
    }

    float co[8][4] = {};                 // O accumulator: 16 rows x 64 cols / warp
    float m_r[2] = {-1e30f, -1e30f};     // rows gid, gid+8
    float l_r[2] = {0.f, 0.f};

    for (int j = 0; j < 4; j++) {
        __syncthreads();  // prev-iter reads of Ks/Vs done before overwrite
        // ---- load K tile (transposed) & V tile (direct) ----
        {
            int kn = tid & 127, kk = (tid >> 7) * 32;
            int krow = j * 128 + kn;
            #pragma unroll
            for (int i = 0; i < 8; i++) {
                float4 v = *(const float4*)&Kp[(size_t)krow * 384 + kk + i * 4];
                Ks[(kk + i * 4 + 0) * QPITCH + kn] = f2tf(v.x);
                Ks[(kk + i * 4 + 1) * QPITCH + kn] = f2tf(v.y);
                Ks[(kk + i * 4 + 2) * QPITCH + kn] = f2tf(v.z);
                Ks[(kk + i * 4 + 3) * QPITCH + kn] = f2tf(v.w);
            }
            int vn = tid >> 1, vc = (tid & 1) * 32;
            int vrow = j * 128 + vn;
            #pragma unroll
            for (int i = 0; i < 8; i++) {
                float4 v = *(const float4*)&Vp[(size_t)vrow * 384 + vc + i * 4];
                float4 w;
                w.x = f2tf(v.x); w.y = f2tf(v.y); w.z = f2tf(v.z); w.w = f2tf(v.w);
                *(float4*)&Vs[vn * VPITCH + vc + i * 4] = w;
            }
        }
        __syncthreads();

        // ---- S = Q @ K^T (warp tile 16 x 128) ----
        float cs[16][4] = {};
        #pragma unroll
        for (int kk = 0; kk < 64; kk += 8) {
            unsigned af[4];
            int mb = wm + gid;
            af[0] = __float_as_uint(Qs[(kk + tig) * QPITCH + mb]);
            af[1] = __float_as_uint(Qs[(kk + tig) * QPITCH + mb + 8]);
            af[2] = __float_as_uint(Qs[(kk + tig + 4) * QPITCH + mb]);
            af[3] = __float_as_uint(Qs[(kk + tig + 4) * QPITCH + mb + 8]);
            #pragma unroll
            for (int ni = 0; ni < 16; ni++) {
                unsigned bf[2];
                int n = ni * 8 + gid;
                bf[0] = __float_as_uint(Ks[(kk + tig) * QPITCH + n]);
                bf[1] = __float_as_uint(Ks[(kk + tig + 4) * QPITCH + n]);
                mma_tf32(cs[ni], af, bf);
            }
        }

        // ---- online softmax (rows fully inside warp: reduce over lane bits 0,1) ----
        float tm0 = -1e30f, tm1 = -1e30f;
        #pragma unroll
        for (int ni = 0; ni < 16; ni++) {
            tm0 = fmaxf(tm0, fmaxf(cs[ni][0], cs[ni][1]));
            tm1 = fmaxf(tm1, fmaxf(cs[ni][2], cs[ni][3]));
        }
        tm0 = fmaxf(tm0, __shfl_xor_sync(0xffffffffu, tm0, 1));
        tm0 = fmaxf(tm0, __shfl_xor_sync(0xffffffffu, tm0, 2));
        tm1 = fmaxf(tm1, __shfl_xor_sync(0xffffffffu, tm1, 1));
        tm1 = fmaxf(tm1, __shfl_xor_sync(0xffffffffu, tm1, 2));
        float nm0 = fmaxf(m_r[0], tm0);
        float nm1 = fmaxf(m_r[1], tm1);
        float a0 = expf(m_r[0] - nm0);
        float a1 = expf(m_r[1] - nm1);
        float ts0 = 0.f, ts1 = 0.f;
        #pragma unroll
        for (int ni = 0; ni < 16; ni++) {
            cs[ni][0] = expf(cs[ni][0] - nm0);
            cs[ni][1] = expf(cs[ni][1] - nm0);
            cs[ni][2] = expf(cs[ni][2] - nm1);
            cs[ni][3] = expf(cs[ni][3] - nm1);
            ts0 += cs[ni][0] + cs[ni][1];
            ts1 += cs[ni][2] + cs[ni][3];
        }
        ts0 += __shfl_xor_sync(0xffffffffu, ts0, 1);
        ts0 += __shfl_xor_sync(0xffffffffu, ts0, 2);
        ts1 += __shfl_xor_sync(0xffffffffu, ts1, 1);
        ts1 += __shfl_xor_sync(0xffffffffu, ts1, 2);
        l_r[0] = l_r[0] * a0 + ts0;
        l_r[1] = l_r[1] * a1 + ts1;
        m_r[0] = nm0;
        m_r[1] = nm1;
        #pragma unroll
        for (int ni = 0; ni < 8; ni++) {
            co[ni][0] *= a0; co[ni][1] *= a0;
            co[ni][2] *= a1; co[ni][3] *= a1;
        }
        // write P tile (tf32, warp-private rows) to SMEM
        {
            int r0 = wm + gid;
            #pragma unroll
            for (int ni = 0; ni < 16; ni++) {
                int c = ni * 8 + tig * 2;
                Ps[r0 * QPITCH + c]           = f2tf(cs[ni][0]);
                Ps[r0 * QPITCH + c + 1]       = f2tf(cs[ni][1]);
                Ps[(r0 + 8) * QPITCH + c]     = f2tf(cs[ni][2]);
                Ps[(r0 + 8) * QPITCH + c + 1] = f2tf(cs[ni][3]);
            }
        }
        __syncwarp();

        // ---- O += P @ V (warp tile 16 x 64) ----
        #pragma unroll
        for (int kk = 0; kk < 128; kk += 8) {
            unsigned af[4];
            int mb = wm + gid;
            af[0] = __float_as_uint(Ps[mb * QPITCH + kk + tig]);
            af[1] = __float_as_uint(Ps[(mb + 8) * QPITCH + kk + tig]);
            af[2] = __float_as_uint(Ps[mb * QPITCH + kk + tig + 4]);
            af[3] = __float_as_uint(Ps[(mb + 8) * QPITCH + kk + tig + 4]);
            #pragma unroll
            for (int ni = 0; ni < 8; ni++) {
                unsigned bf[2];
                int n = ni * 8 + gid;
                bf[0] = __float_as_uint(Vs[(kk + tig) * VPITCH + n]);
                bf[1] = __float_as_uint(Vs[(kk + tig + 4) * VPITCH + n]);
                mma_tf32(co[ni], af, bf);
            }
        }
    }

    // ---- normalize and store ----
    {
        float inv0 = 1.f / l_r[0];
        float inv1 = 1.f / l_r[1];
        int r0 = bm + wm + gid;
        #pragma unroll
        for (int ni = 0; ni < 8; ni++) {
            int col = ni * 8 + tig * 2;
            *(float2*)&Cp[(size_t)r0 * ND + col] =
                make_float2(co[ni][0] * inv0, co[ni][1] * inv0);
            *(float2*)&Cp[(size_t)(r0 + 8) * ND + col] =
                make_float2(co[ni][2] * inv1, co[ni][3] * inv1);
        }
    }
}

// ---------------- launch ----------------
extern "C" void kernel_launch(void* const* d_in, const int* in_sizes, int n_in,
                              void* d_out, int out_size) {
    const int*   src    = (const int*)d_in[0];
    const int*   dst    = (const int*)d_in[1];
    const float* w1     = (const float*)d_in[2];
    const float* b1     = (const float*)d_in[3];
    const float* w2     = (const float*)d_in[4];
    const float* b2     = (const float*)d_in[5];
    const float* proj_w = (const float*)d_in[6];
    const float* proj_b = (const float*)d_in[7];
    const float* ln1_g  = (const float*)d_in[8];
    const float* ln1_b  = (const float*)d_in[9];
    const float* w_qkv  = (const float*)d_in[10];
    const float* b_qkv  = (const float*)d_in[11];
    const float* w_o    = (const float*)d_in[12];
    const float* b_o    = (const float*)d_in[13];
    const float* ln2_g  = (const float*)d_in[14];
    const float* ln2_b  = (const float*)d_in[15];
    const float* w_ff1  = (const float*)d_in[16];
    const float* b_ff1  = (const float*)d_in[17];
    const float* w_ff2  = (const float*)d_in[18];
    const float* b_ff2  = (const float*)d_in[19];
    float* out = (float*)d_out;

    cudaFuncSetAttribute(flash_tf32, cudaFuncAttributeMaxDynamicSharedMemorySize, SM_TOT);

    // precompute fused encode+proj table
    k_W    <<<ND, ND>>>(w2, proj_w);
    k_bias <<<1, ND>>>(b2, proj_w, proj_b);
    k_table<<<513, ND>>>(w1, b1);

    // co-occurrence counts + feature build (both streams)
    k_cooc<<<NB, NL>>>(src, dst);
    k_feat<<<(NTOK * ND) / 256, 256>>>();

    // transformer (both streams batched: 65536 tokens)
    k_ln<<<NTOK, ND>>>(BUF_X, BUF_H, ln1_g, ln1_b);
    gemm_tf32<<<dim3(6, NTOK / 128), 256>>>(BUF_H, w_qkv, b_qkv, -1, BUF_QKV, nullptr,
                                            NTOK, 384, 128, 0);
    flash_tf32<<<dim3(NL / 128, NHB), 256, SM_TOT>>>();
    gemm_tf32<<<dim3(2, NTOK / 128), 256>>>(BUF_CTX, w_o, b_o, BUF_X, BUF_X, nullptr,
                                            NTOK, 128, 128, 0);
    k_ln<<<NTOK, ND>>>(BUF_X, BUF_H, ln2_g, ln2_b);
    gemm_tf32<<<dim3(8, NTOK / 128), 256>>>(BUF_H, w_ff1, b_ff1, -1, BUF_FF, nullptr,
                                            NTOK, 512, 128, 1);
    gemm_tf32<<<dim3(2, NTOK / 128), 256>>>(BUF_FF, w_ff2, b_ff2, BUF_X, BUF_X, out,
                                            NTOK, 128, 512, 0);
}

// round 7
// speedup vs baseline: 2.0743x; 1.1328x over previous
#include <cuda_runtime.h>
#include <math.h>

#define NB    64
#define NL    512
#define ND    128
#define TOKS  32768          // B*L per stream
#define NTOK  65536          // 2*B*L
#define NHB   256            // 2*B*H attention batches

// ---------------- scratch (device globals; no allocation allowed) ----------------
__device__ int   g_cnt[NTOK * 2];
__device__ float g_W[ND * ND];
__device__ float g_biasT[ND];
__device__ float g_T2[513 * ND];
__device__ float g_X[(size_t)NTOK * ND];
__device__ float g_H[(size_t)NTOK * ND];
__device__ float g_QKV[(size_t)NTOK * 3 * ND];
__device__ float g_CTX[(size_t)NTOK * ND];
__device__ float g_FF[(size_t)NTOK * 4 * ND];

#define BUF_X    0
#define BUF_H    1
#define BUF_QKV  2
#define BUF_CTX  3
#define BUF_FF   4
__device__ __forceinline__ float* buf(int id) {
    switch (id) {
        case BUF_X:   return g_X;
        case BUF_H:   return g_H;
        case BUF_QKV: return g_QKV;
        case BUF_CTX: return g_CTX;
        default:      return g_FF;
    }
}

// fp32 -> tf32 (round to nearest)
__device__ __forceinline__ float f2tf(float x) {
    unsigned r;
    asm("cvt.rna.tf32.f32 %0, %1;" : "=r"(r) : "f"(x));
    return __uint_as_float(r);
}

__device__ __forceinline__ void mma_tf32(float* c, const unsigned* a, const unsigned* b) {
    asm volatile(
        "mma.sync.aligned.m16n8k8.row.col.f32.tf32.tf32.f32 "
        "{%0,%1,%2,%3}, {%4,%5,%6,%7}, {%8,%9}, {%0,%1,%2,%3};"
        : "+f"(c[0]), "+f"(c[1]), "+f"(c[2]), "+f"(c[3])
        : "r"(a[0]), "r"(a[1]), "r"(a[2]), "r"(a[3]), "r"(b[0]), "r"(b[1]));
}

__device__ __forceinline__ void cp_async16(float* smem_dst, const float* gsrc) {
    unsigned saddr = (unsigned)__cvta_generic_to_shared(smem_dst);
    asm volatile("cp.async.cg.shared.global [%0], [%1], 16;" :: "r"(saddr), "l"(gsrc));
}

// ---------------- tiny precompute kernels ----------------
__global__ void k_W(const float* __restrict__ w2, const float* __restrict__ proj_w) {
    int k = blockIdx.x, d = threadIdx.x;
    float acc = 0.f;
    #pragma unroll 8
    for (int j = 0; j < ND; j++) acc += w2[k * ND + j] * proj_w[j * ND + d];
    g_W[k * ND + d] = acc;
}

__global__ void k_bias(const float* __restrict__ b2, const float* __restrict__ proj_w,
                       const float* __restrict__ proj_b) {
    int d = threadIdx.x;
    float acc = proj_b[d];
    #pragma unroll 8
    for (int k = 0; k < ND; k++) acc += 2.f * b2[k] * proj_w[k * ND + d];
    g_biasT[d] = acc;
}

__global__ void k_table(const float* __restrict__ w1, const float* __restrict__ b1) {
    __shared__ float h[ND];
    int c = blockIdx.x, d = threadIdx.x;
    h[d] = fmaxf((float)c * w1[d] + b1[d], 0.f);
    __syncthreads();
    float acc = 0.5f * g_biasT[d];
    #pragma unroll 8
    for (int k = 0; k < ND; k++) acc += h[k] * g_W[k * ND + d];
    g_T2[c * ND + d] = acc;
}

// ---------------- co-occurrence counts ----------------
__global__ void k_cooc(const int* __restrict__ src, const int* __restrict__ dst) {
    __shared__ int ss[NL], dd[NL];
    int b = blockIdx.x, i = threadIdx.x;
    ss[i] = src[b * NL + i];
    dd[i] = dst[b * NL + i];
    __syncthreads();
    int qs = ss[i], qd = dd[i];
    int css = 0, csd = 0, cds = 0, cdd = 0;
    #pragma unroll 8
    for (int j = 0; j < NL; j++) {
        int s = ss[j], t = dd[j];
        css += (qs == s); csd += (qs == t);
        cds += (qd == s); cdd += (qd == t);
    }
    if (qs == 0) { css = 0; csd = 0; }
    if (qd == 0) { cds = 0; cdd = 0; }
    int ts = b * NL + i, td = TOKS + b * NL + i;
    g_cnt[ts * 2 + 0] = css; g_cnt[ts * 2 + 1] = csd;
    g_cnt[td * 2 + 0] = cds; g_cnt[td * 2 + 1] = cdd;
}

__global__ void k_feat() {
    int idx = blockIdx.x * 256 + threadIdx.x;
    int t = idx >> 7, d = idx & 127;
    int c0 = g_cnt[t * 2], c1 = g_cnt[t * 2 + 1];
    g_X[idx] = g_T2[c0 * ND + d] + g_T2[c1 * ND + d];
}

// ---------------- layernorm ----------------
__global__ void k_ln(int xid, int yid,
                     const float* __restrict__ g, const float* __restrict__ b) {
    const float* x = buf(xid);
    float* y = buf(yid);
    int row = blockIdx.x, t = threadIdx.x;
    float v = x[(size_t)row * ND + t];
    __shared__ float sh[4];
    float s = v;
    for (int o = 16; o; o >>= 1) s += __shfl_xor_sync(0xffffffffu, s, o);
    int w = t >> 5;
    if ((t & 31) == 0) sh[w] = s;
    __syncthreads();
    float mu = (sh[0] + sh[1] + sh[2] + sh[3]) * (1.f / 128.f);
    __syncthreads();
    float dlt = v - mu;
    float s2 = dlt * dlt;
    for (int o = 16; o; o >>= 1) s2 += __shfl_xor_sync(0xffffffffu, s2, o);
    if ((t & 31) == 0) sh[w] = s2;
    __syncthreads();
    float var = (sh[0] + sh[1] + sh[2] + sh[3]) * (1.f / 128.f);
    float r = rsqrtf(var + 1e-5f);
    y[(size_t)row * ND + t] = dlt * r * g[t] + b[t];
}

// ============ tf32 GEMM, cp.async double-buffered: C = act(A@B + bias) + res ============
// Block tile 128x128, BK=16, 256 thr = 8 warps (4m x 2n), warp tile 32x64.
// As[m][k] pitch 20 (conflict-free A-frag LDS), Bs[k][n] pitch 136 (conflict-free B-frag LDS).
#define AP 20
#define BP 136
__global__ __launch_bounds__(256, 2) void gemm_tf32(
        int Aid, const float* __restrict__ Bm,
        const float* __restrict__ bias, int resid,
        int Cid, float* __restrict__ cext,
        int M, int N, int K, int act) {
    const float* A = buf(Aid);
    const float* res = (resid >= 0) ? buf(resid) : nullptr;
    float* C = cext ? cext : buf(Cid);
    __shared__ float As[2][128 * AP];
    __shared__ float Bs[2][16 * BP];
    int tid = threadIdx.x;
    int lane = tid & 31, warp = tid >> 5;
    int wm = (warp >> 1) * 32, wn = (warp & 1) * 64;
    int gid = lane >> 2, tig = lane & 3;
    int bm = blockIdx.y * 128, bn = blockIdx.x * 128;

    // cp.async mappings: A 128 rows x 64B (2 x 16B per thread), B 16 rows x 512B.
    int a_row = tid >> 1, a_kc = (tid & 1) * 8;
    int b_row = tid >> 4, b_nc = (tid & 15) * 8;

    int nk = K / 16;
    // prologue: stage 0
    {
        const float* ga = &A[(size_t)(bm + a_row) * K + a_kc];
        cp_async16(&As[0][a_row * AP + a_kc], ga);
        cp_async16(&As[0][a_row * AP + a_kc + 4], ga + 4);
        const float* gb = &Bm[(size_t)b_row * N + bn + b_nc];
        cp_async16(&Bs[0][b_row * BP + b_nc], gb);
        cp_async16(&Bs[0][b_row * BP + b_nc + 4], gb + 4);
        asm volatile("cp.async.commit_group;");
    }

    float acc[2][8][4] = {};
    for (int it = 0; it < nk; it++) {
        int cur = it & 1;
        if (it + 1 < nk) {
            int nxt = (it + 1) & 1, k0 = (it + 1) * 16;
            const float* ga = &A[(size_t)(bm + a_row) * K + k0 + a_kc];
            cp_async16(&As[nxt][a_row * AP + a_kc], ga);
            cp_async16(&As[nxt][a_row * AP + a_kc + 4], ga + 4);
            const float* gb = &Bm[(size_t)(k0 + b_row) * N + bn + b_nc];
            cp_async16(&Bs[nxt][b_row * BP + b_nc], gb);
            cp_async16(&Bs[nxt][b_row * BP + b_nc + 4], gb + 4);
            asm volatile("cp.async.commit_group;");
            asm volatile("cp.async.wait_group 1;");
        } else {
            asm volatile("cp.async.wait_group 0;");
        }
        __syncthreads();
        #pragma unroll
        for (int kk = 0; kk < 16; kk += 8) {
            unsigned af[2][4], bf[8][2];
            #pragma unroll
            for (int mi = 0; mi < 2; mi++) {
                int mb = wm + mi * 16 + gid;
                af[mi][0] = __float_as_uint(f2tf(As[cur][mb * AP + kk + tig]));
                af[mi][1] = __float_as_uint(f2tf(As[cur][(mb + 8) * AP + kk + tig]));
                af[mi][2] = __float_as_uint(f2tf(As[cur][mb * AP + kk + tig + 4]));
                af[mi][3] = __float_as_uint(f2tf(As[cur][(mb + 8) * AP + kk + tig + 4]));
            }
            #pragma unroll
            for (int ni = 0; ni < 8; ni++) {
                int n = wn + ni * 8 + gid;
                bf[ni][0] = __float_as_uint(f2tf(Bs[cur][(kk + tig) * BP + n]));
                bf[ni][1] = __float_as_uint(f2tf(Bs[cur][(kk + tig + 4) * BP + n]));
            }
            #pragma unroll
            for (int mi = 0; mi < 2; mi++)
                #pragma unroll
                for (int ni = 0; ni < 8; ni++)
                    mma_tf32(acc[mi][ni], af[mi], bf[ni]);
        }
        __syncthreads();  // all reads of 'cur' done before it is overwritten
    }

    #pragma unroll
    for (int mi = 0; mi < 2; mi++) {
        int r0 = bm + wm + mi * 16 + gid;
        #pragma unroll
        for (int ni = 0; ni < 8; ni++) {
            int col = bn + wn + ni * 8 + tig * 2;
            float x0 = acc[mi][ni][0], x1 = acc[mi][ni][1];
            float x2 = acc[mi][ni][2], x3 = acc[mi][ni][3];
            if (bias) {
                float bb0 = bias[col], bb1 = bias[col + 1];
                x0 += bb0; x1 += bb1; x2 += bb0; x3 += bb1;
            }
            if (act) {
                x0 = 0.5f * x0 * (1.f + erff(x0 * 0.70710678118654752f));
                x1 = 0.5f * x1 * (1.f + erff(x1 * 0.70710678118654752f));
                x2 = 0.5f * x2 * (1.f + erff(x2 * 0.70710678118654752f));
                x3 = 0.5f * x3 * (1.f + erff(x3 * 0.70710678118654752f));
            }
            if (res) {
                x0 += res[(size_t)r0 * N + col];       x1 += res[(size_t)r0 * N + col + 1];
                x2 += res[(size_t)(r0 + 8) * N + col]; x3 += res[(size_t)(r0 + 8) * N + col + 1];
            }
            *(float2*)&C[(size_t)r0 * N + col] = make_float2(x0, x1);
            *(float2*)&C[(size_t)(r0 + 8) * N + col] = make_float2(x2, x3);
        }
    }
}

// ============ fused flash attention (tf32): ctx = softmax(Q K^T / 8) V ============
// Grid: (NL/128, NHB). CTA: 256 threads = 8 warps, EACH WARP OWNS 16 FULL ROWS.
#define QPITCH 132
#define VPITCH 68
#define SM_Q   0
#define SM_K   (64 * QPITCH)
#define SM_V   (SM_K + 64 * QPITCH)
#define SM_P   (SM_V + 128 * VPITCH)
#define SM_TOT ((SM_P + 128 * QPITCH) * 4)

__global__ __launch_bounds__(256, 1) void flash_tf32() {
    extern __shared__ float sm[];
    float* Qs = sm + SM_Q;
    float* Ks = sm + SM_K;
    float* Vs = sm + SM_V;
    float* Ps = sm + SM_P;

    int z = blockIdx.y;
    int sb = z >> 1, h = z & 1;
    const float* Qp = g_QKV + (size_t)sb * NL * 384 + h * 64;
    const float* Kp = Qp + 128;
    const float* Vp = Qp + 256;
    float* Cp = g_CTX + (size_t)sb * NL * ND + h * 64;

    int bm = blockIdx.x * 128;
    int tid = threadIdx.x, lane = tid & 31, warp = tid >> 5;
    int wm = warp * 16;
    int gid = lane >> 2, tig = lane & 3;

    {
        int qm = tid & 127, qk = (tid >> 7) * 32;
        #pragma unroll
        for (int i = 0; i < 8; i++) {
            float4 v = *(const float4*)&Qp[(size_t)(bm + qm) * 384 + qk + i * 4];
            Qs[(qk + i * 4 + 0) * QPITCH + qm] = f2tf(v.x * 0.125f);
            Qs[(qk + i * 4 + 1) * QPITCH + qm] = f2tf(v.y * 0.125f);
            Qs[(qk + i * 4 + 2) * QPITCH + qm] = f2tf(v.z * 0.125f);
            Qs[(qk + i * 4 + 3) * QPITCH + qm] = f2tf(v.w * 0.125f);
        }
    }

    float co[8][4] = {};
    float m_r[2] = {-1e30f, -1e30f};
    float l_r[2] = {0.f, 0.f};

    for (int j = 0; j < 4; j++) {
        __syncthreads();
        {
            int kn = tid & 127, kk = (tid >> 7) * 32;
            int krow = j * 128 + kn;
            #pragma unroll
            for (int i = 0; i < 8; i++) {
                float4 v = *(const float4*)&Kp[(size_t)krow * 384 + kk + i * 4];
                Ks[(kk + i * 4 + 0) * QPITCH + kn] = f2tf(v.x);
                Ks[(kk + i * 4 + 1) * QPITCH + kn] = f2tf(v.y);
                Ks[(kk + i * 4 + 2) * QPITCH + kn] = f2tf(v.z);
                Ks[(kk + i * 4 + 3) * QPITCH + kn] = f2tf(v.w);
            }
            int vn = tid >> 1, vc = (tid & 1) * 32;
            int vrow = j * 128 + vn;
            #pragma unroll
            for (int i = 0; i < 8; i++) {
                float4 v = *(const float4*)&Vp[(size_t)vrow * 384 + vc + i * 4];
                float4 w;
                w.x = f2tf(v.x); w.y = f2tf(v.y); w.z = f2tf(v.z); w.w = f2tf(v.w);
                *(float4*)&Vs[vn * VPITCH + vc + i * 4] = w;
            }
        }
        __syncthreads();

        float cs[16][4] = {};
        #pragma unroll
        for (int kk = 0; kk < 64; kk += 8) {
            unsigned af[4];
            int mb = wm + gid;
            af[0] = __float_as_uint(Qs[(kk + tig) * QPITCH + mb]);
            af[1] = __float_as_uint(Qs[(kk + tig) * QPITCH + mb + 8]);
            af[2] = __float_as_uint(Qs[(kk + tig + 4) * QPITCH + mb]);
            af[3] = __float_as_uint(Qs[(kk + tig + 4) * QPITCH + mb + 8]);
            #pragma unroll
            for (int ni = 0; ni < 16; ni++) {
                unsigned bf[2];
                int n = ni * 8 + gid;
                bf[0] = __float_as_uint(Ks[(kk + tig) * QPITCH + n]);
                bf[1] = __float_as_uint(Ks[(kk + tig + 4) * QPITCH + n]);
                mma_tf32(cs[ni], af, bf);
            }
        }

        float tm0 = -1e30f, tm1 = -1e30f;
        #pragma unroll
        for (int ni = 0; ni < 16; ni++) {
            tm0 = fmaxf(tm0, fmaxf(cs[ni][0], cs[ni][1]));
            tm1 = fmaxf(tm1, fmaxf(cs[ni][2], cs[ni][3]));
        }
        tm0 = fmaxf(tm0, __shfl_xor_sync(0xffffffffu, tm0, 1));
        tm0 = fmaxf(tm0, __shfl_xor_sync(0xffffffffu, tm0, 2));
        tm1 = fmaxf(tm1, __shfl_xor_sync(0xffffffffu, tm1, 1));
        tm1 = fmaxf(tm1, __shfl_xor_sync(0xffffffffu, tm1, 2));
        float nm0 = fmaxf(m_r[0], tm0);
        float nm1 = fmaxf(m_r[1], tm1);
        float a0 = expf(m_r[0] - nm0);
        float a1 = expf(m_r[1] - nm1);
        float ts0 = 0.f, ts1 = 0.f;
        #pragma unroll
        for (int ni = 0; ni < 16; ni++) {
            cs[ni][0] = expf(cs[ni][0] - nm0);
            cs[ni][1] = expf(cs[ni][1] - nm0);
            cs[ni][2] = expf(cs[ni][2] - nm1);
            cs[ni][3] = expf(cs[ni][3] - nm1);
            ts0 += cs[ni][0] + cs[ni][1];
            ts1 += cs[ni][2] + cs[ni][3];
        }
        ts0 += __shfl_xor_sync(0xffffffffu, ts0, 1);
        ts0 += __shfl_xor_sync(0xffffffffu, ts0, 2);
        ts1 += __shfl_xor_sync(0xffffffffu, ts1, 1);
        ts1 += __shfl_xor_sync(0xffffffffu, ts1, 2);
        l_r[0] = l_r[0] * a0 + ts0;
        l_r[1] = l_r[1] * a1 + ts1;
        m_r[0] = nm0;
        m_r[1] = nm1;
        #pragma unroll
        for (int ni = 0; ni < 8; ni++) {
            co[ni][0] *= a0; co[ni][1] *= a0;
            co[ni][2] *= a1; co[ni][3] *= a1;
        }
        {
            int r0 = wm + gid;
            #pragma unroll
            for (int ni = 0; ni < 16; ni++) {
                int c = ni * 8 + tig * 2;
                Ps[r0 * QPITCH + c]           = f2tf(cs[ni][0]);
                Ps[r0 * QPITCH + c + 1]       = f2tf(cs[ni][1]);
                Ps[(r0 + 8) * QPITCH + c]     = f2tf(cs[ni][2]);
                Ps[(r0 + 8) * QPITCH + c + 1] = f2tf(cs[ni][3]);
            }
        }
        __syncwarp();

        #pragma unroll
        for (int kk = 0; kk < 128; kk += 8) {
            unsigned af[4];
            int mb = wm + gid;
            af[0] = __float_as_uint(Ps[mb * QPITCH + kk + tig]);
            af[1] = __float_as_uint(Ps[(mb + 8) * QPITCH + kk + tig]);
            af[2] = __float_as_uint(Ps[mb * QPITCH + kk + tig + 4]);
            af[3] = __float_as_uint(Ps[(mb + 8) * QPITCH + kk + tig + 4]);
            #pragma unroll
            for (int ni = 0; ni < 8; ni++) {
                unsigned bf[2];
                int n = ni * 8 + gid;
                bf[0] = __float_as_uint(Vs[(kk + tig) * VPITCH + n]);
                bf[1] = __float_as_uint(Vs[(kk + tig + 4) * VPITCH + n]);
                mma_tf32(co[ni], af, bf);
            }
        }
    }

    {
        float inv0 = 1.f / l_r[0];
        float inv1 = 1.f / l_r[1];
        int r0 = bm + wm + gid;
        #pragma unroll
        for (int ni = 0; ni < 8; ni++) {
            int col = ni * 8 + tig * 2;
            *(float2*)&Cp[(size_t)r0 * ND + col] =
                make_float2(co[ni][0] * inv0, co[ni][1] * inv0);
            *(float2*)&Cp[(size_t)(r0 + 8) * ND + col] =
                make_float2(co[ni][2] * inv1, co[ni][3] * inv1);
        }
    }
}

// ---------------- launch ----------------
extern "C" void kernel_launch(void* const* d_in, const int* in_sizes, int n_in,
                              void* d_out, int out_size) {
    const int*   src    = (const int*)d_in[0];
    const int*   dst    = (const int*)d_in[1];
    const float* w1     = (const float*)d_in[2];
    const float* b1     = (const float*)d_in[3];
    const float* w2     = (const float*)d_in[4];
    const float* b2     = (const float*)d_in[5];
    const float* proj_w = (const float*)d_in[6];
    const float* proj_b = (const float*)d_in[7];
    const float* ln1_g  = (const float*)d_in[8];
    const float* ln1_b  = (const float*)d_in[9];
    const float* w_qkv  = (const float*)d_in[10];
    const float* b_qkv  = (const float*)d_in[11];
    const float* w_o    = (const float*)d_in[12];
    const float* b_o    = (const float*)d_in[13];
    const float* ln2_g  = (const float*)d_in[14];
    const float* ln2_b  = (const float*)d_in[15];
    const float* w_ff1  = (const float*)d_in[16];
    const float* b_ff1  = (const float*)d_in[17];
    const float* w_ff2  = (const float*)d_in[18];
    const float* b_ff2  = (const float*)d_in[19];
    float* out = (float*)d_out;

    cudaFuncSetAttribute(flash_tf32, cudaFuncAttributeMaxDynamicSharedMemorySize, SM_TOT);

    // precompute fused encode+proj table
    k_W    <<<ND, ND>>>(w2, proj_w);
    k_bias <<<1, ND>>>(b2, proj_w, proj_b);
    k_table<<<513, ND>>>(w1, b1);

    // co-occurrence counts + feature build (both streams)
    k_cooc<<<NB, NL>>>(src, dst);
    k_feat<<<(NTOK * ND) / 256, 256>>>();

    // transformer (both streams batched: 65536 tokens)
    k_ln<<<NTOK, ND>>>(BUF_X, BUF_H, ln1_g, ln1_b);
    gemm_tf32<<<dim3(3, NTOK / 128), 256>>>(BUF_H, w_qkv, b_qkv, -1, BUF_QKV, nullptr,
                                            NTOK, 384, 128, 0);
    flash_tf32<<<dim3(NL / 128, NHB), 256, SM_TOT>>>();
    gemm_tf32<<<dim3(1, NTOK / 128), 256>>>(BUF_CTX, w_o, b_o, BUF_X, BUF_X, nullptr,
                                            NTOK, 128, 128, 0);
    k_ln<<<NTOK, ND>>>(BUF_X, BUF_H, ln2_g, ln2_b);
    gemm_tf32<<<dim3(4, NTOK / 128), 256>>>(BUF_H, w_ff1, b_ff1, -1, BUF_FF, nullptr,
                                            NTOK, 512, 128, 1);
    gemm_tf32<<<dim3(1, NTOK / 128), 256>>>(BUF_FF, w_ff2, b_ff2, BUF_X, BUF_X, out,
                                            NTOK, 128, 512, 0);
}

// round 9
// speedup vs baseline: 2.1144x; 1.0193x over previous
#include <cuda_runtime.h>
#include <math.h>

#define NB    64
#define NL    512
#define ND    128
#define TOKS  32768          // B*L per stream
#define NTOK  65536          // 2*B*L
#define NHB   256            // 2*B*H attention batches

// ---------------- scratch (device globals; no allocation allowed) ----------------
__device__ int   g_cnt[NTOK * 2];
__device__ float g_W[ND * ND];
__device__ float g_biasT[ND];
__device__ float g_T2[513 * ND];
__device__ float g_X[(size_t)NTOK * ND];
__device__ float g_H[(size_t)NTOK * ND];
__device__ float g_QKV[(size_t)NTOK * 3 * ND];
__device__ float g_CTX[(size_t)NTOK * ND];
__device__ float g_FF[(size_t)NTOK * 4 * ND];

#define BUF_X    0
#define BUF_H    1
#define BUF_QKV  2
#define BUF_CTX  3
#define BUF_FF   4
__device__ __forceinline__ float* buf(int id) {
    switch (id) {
        case BUF_X:   return g_X;
        case BUF_H:   return g_H;
        case BUF_QKV: return g_QKV;
        case BUF_CTX: return g_CTX;
        default:      return g_FF;
    }
}

// fp32 -> tf32 (round to nearest)
__device__ __forceinline__ float f2tf(float x) {
    unsigned r;
    asm("cvt.rna.tf32.f32 %0, %1;" : "=r"(r) : "f"(x));
    return __uint_as_float(r);
}

__device__ __forceinline__ void mma_tf32(float* c, const unsigned* a, const unsigned* b) {
    asm volatile(
        "mma.sync.aligned.m16n8k8.row.col.f32.tf32.tf32.f32 "
        "{%0,%1,%2,%3}, {%4,%5,%6,%7}, {%8,%9}, {%0,%1,%2,%3};"
        : "+f"(c[0]), "+f"(c[1]), "+f"(c[2]), "+f"(c[3])
        : "r"(a[0]), "r"(a[1]), "r"(a[2]), "r"(a[3]), "r"(b[0]), "r"(b[1]));
}

__device__ __forceinline__ void cp_async16(float* smem_dst, const float* gsrc) {
    unsigned saddr = (unsigned)__cvta_generic_to_shared(smem_dst);
    asm volatile("cp.async.cg.shared.global [%0], [%1], 16;" :: "r"(saddr), "l"(gsrc));
}

// ---------------- tiny precompute kernels ----------------
__global__ void k_W(const float* __restrict__ w2, const float* __restrict__ proj_w) {
    int k = blockIdx.x, d = threadIdx.x;
    float acc = 0.f;
    #pragma unroll 8
    for (int j = 0; j < ND; j++) acc += w2[k * ND + j] * proj_w[j * ND + d];
    g_W[k * ND + d] = acc;
}

__global__ void k_bias(const float* __restrict__ b2, const float* __restrict__ proj_w,
                       const float* __restrict__ proj_b) {
    int d = threadIdx.x;
    float acc = proj_b[d];
    #pragma unroll 8
    for (int k = 0; k < ND; k++) acc += 2.f * b2[k] * proj_w[k * ND + d];
    g_biasT[d] = acc;
}

__global__ void k_table(const float* __restrict__ w1, const float* __restrict__ b1) {
    __shared__ float h[ND];
    int c = blockIdx.x, d = threadIdx.x;
    h[d] = fmaxf((float)c * w1[d] + b1[d], 0.f);
    __syncthreads();
    float acc = 0.5f * g_biasT[d];
    #pragma unroll 8
    for (int k = 0; k < ND; k++) acc += h[k] * g_W[k * ND + d];
    g_T2[c * ND + d] = acc;
}

// ---------------- co-occurrence counts ----------------
__global__ void k_cooc(const int* __restrict__ src, const int* __restrict__ dst) {
    __shared__ int ss[NL], dd[NL];
    int b = blockIdx.x, i = threadIdx.x;
    ss[i] = src[b * NL + i];
    dd[i] = dst[b * NL + i];
    __syncthreads();
    int qs = ss[i], qd = dd[i];
    int css = 0, csd = 0, cds = 0, cdd = 0;
    #pragma unroll 8
    for (int j = 0; j < NL; j++) {
        int s = ss[j], t = dd[j];
        css += (qs == s); csd += (qs == t);
        cds += (qd == s); cdd += (qd == t);
    }
    if (qs == 0) { css = 0; csd = 0; }
    if (qd == 0) { cds = 0; cdd = 0; }
    int ts = b * NL + i, td = TOKS + b * NL + i;
    g_cnt[ts * 2 + 0] = css; g_cnt[ts * 2 + 1] = csd;
    g_cnt[td * 2 + 0] = cds; g_cnt[td * 2 + 1] = cdd;
}

__global__ void k_feat() {
    int idx = blockIdx.x * 256 + threadIdx.x;
    int t = idx >> 7, d = idx & 127;
    int c0 = g_cnt[t * 2], c1 = g_cnt[t * 2 + 1];
    g_X[idx] = g_T2[c0 * ND + d] + g_T2[c1 * ND + d];
}

// ---------------- layernorm ----------------
__global__ void k_ln(int xid, int yid,
                     const float* __restrict__ g, const float* __restrict__ b) {
    const float* x = buf(xid);
    float* y = buf(yid);
    int row = blockIdx.x, t = threadIdx.x;
    float v = x[(size_t)row * ND + t];
    __shared__ float sh[4];
    float s = v;
    for (int o = 16; o; o >>= 1) s += __shfl_xor_sync(0xffffffffu, s, o);
    int w = t >> 5;
    if ((t & 31) == 0) sh[w] = s;
    __syncthreads();
    float mu = (sh[0] + sh[1] + sh[2] + sh[3]) * (1.f / 128.f);
    __syncthreads();
    float dlt = v - mu;
    float s2 = dlt * dlt;
    for (int o = 16; o; o >>= 1) s2 += __shfl_xor_sync(0xffffffffu, s2, o);
    if ((t & 31) == 0) sh[w] = s2;
    __syncthreads();
    float var = (sh[0] + sh[1] + sh[2] + sh[3]) * (1.f / 128.f);
    float r = rsqrtf(var + 1e-5f);
    y[(size_t)row * ND + t] = dlt * r * g[t] + b[t];
}

// ============ tf32 GEMM, 3-stage cp.async pipeline: C = act(A@B + bias) + res ============
// Block tile 128x128, BK=16, 256 thr = 8 warps (4m x 2n), warp tile 32x64.
// SMEM is DYNAMIC (56832 B > 48 KB static limit): As[NSTG][128*AP] then Bs[NSTG][16*BP].
#define AP 20
#define BP 136
#define NSTG 3
#define GEMM_SMEM ((NSTG * 128 * AP + NSTG * 16 * BP) * 4)
__global__ __launch_bounds__(256, 2) void gemm_tf32(
        int Aid, const float* __restrict__ Bm,
        const float* __restrict__ bias, int resid,
        int Cid, float* __restrict__ cext,
        int M, int N, int K, int act) {
    const float* A = buf(Aid);
    const float* res = (resid >= 0) ? buf(resid) : nullptr;
    float* C = cext ? cext : buf(Cid);
    extern __shared__ float gsm[];
    float* Asm = gsm;                         // [NSTG][128*AP]
    float* Bsm = gsm + NSTG * 128 * AP;       // [NSTG][16*BP]
    int tid = threadIdx.x;
    int lane = tid & 31, warp = tid >> 5;
    int wm = (warp >> 1) * 32, wn = (warp & 1) * 64;
    int gid = lane >> 2, tig = lane & 3;
    int bm = blockIdx.y * 128, bn = blockIdx.x * 128;

    int a_row = tid >> 1, a_kc = (tid & 1) * 8;
    int b_row = tid >> 4, b_nc = (tid & 15) * 8;

    int nk = K / 16;
    // prologue: stages 0 and 1
    #pragma unroll
    for (int p = 0; p < 2; p++) {
        if (p < nk) {
            int k0 = p * 16;
            const float* ga = &A[(size_t)(bm + a_row) * K + k0 + a_kc];
            cp_async16(&Asm[p * 128 * AP + a_row * AP + a_kc], ga);
            cp_async16(&Asm[p * 128 * AP + a_row * AP + a_kc + 4], ga + 4);
            const float* gb = &Bm[(size_t)(k0 + b_row) * N + bn + b_nc];
            cp_async16(&Bsm[p * 16 * BP + b_row * BP + b_nc], gb);
            cp_async16(&Bsm[p * 16 * BP + b_row * BP + b_nc + 4], gb + 4);
            asm volatile("cp.async.commit_group;");
        }
    }

    float acc[2][8][4] = {};
    for (int it = 0; it < nk; it++) {
        if (it + 1 < nk) asm volatile("cp.async.wait_group 1;");
        else             asm volatile("cp.async.wait_group 0;");
        __syncthreads();   // stage 'it' visible to all; stage it-1 (== it+2 mod 3) fully consumed
        // prefetch stage it+2 (overwrites slot of stage it-1)
        if (it + 2 < nk) {
            int nxt = (it + 2) % NSTG, k0 = (it + 2) * 16;
            const float* ga = &A[(size_t)(bm + a_row) * K + k0 + a_kc];
            cp_async16(&Asm[nxt * 128 * AP + a_row * AP + a_kc], ga);
            cp_async16(&Asm[nxt * 128 * AP + a_row * AP + a_kc + 4], ga + 4);
            const float* gb = &Bm[(size_t)(k0 + b_row) * N + bn + b_nc];
            cp_async16(&Bsm[nxt * 16 * BP + b_row * BP + b_nc], gb);
            cp_async16(&Bsm[nxt * 16 * BP + b_row * BP + b_nc + 4], gb + 4);
            asm volatile("cp.async.commit_group;");
        }
        const float* As = Asm + (it % NSTG) * 128 * AP;
        const float* Bs = Bsm + (it % NSTG) * 16 * BP;
        #pragma unroll
        for (int kk = 0; kk < 16; kk += 8) {
            unsigned af[2][4], bf[8][2];
            #pragma unroll
            for (int mi = 0; mi < 2; mi++) {
                int mb = wm + mi * 16 + gid;
                af[mi][0] = __float_as_uint(f2tf(As[mb * AP + kk + tig]));
                af[mi][1] = __float_as_uint(f2tf(As[(mb + 8) * AP + kk + tig]));
                af[mi][2] = __float_as_uint(f2tf(As[mb * AP + kk + tig + 4]));
                af[mi][3] = __float_as_uint(f2tf(As[(mb + 8) * AP + kk + tig + 4]));
            }
            #pragma unroll
            for (int ni = 0; ni < 8; ni++) {
                int n = wn + ni * 8 + gid;
                bf[ni][0] = __float_as_uint(f2tf(Bs[(kk + tig) * BP + n]));
                bf[ni][1] = __float_as_uint(f2tf(Bs[(kk + tig + 4) * BP + n]));
            }
            #pragma unroll
            for (int mi = 0; mi < 2; mi++)
                #pragma unroll
                for (int ni = 0; ni < 8; ni++)
                    mma_tf32(acc[mi][ni], af[mi], bf[ni]);
        }
    }

    #pragma unroll
    for (int mi = 0; mi < 2; mi++) {
        int r0 = bm + wm + mi * 16 + gid;
        #pragma unroll
        for (int ni = 0; ni < 8; ni++) {
            int col = bn + wn + ni * 8 + tig * 2;
            float x0 = acc[mi][ni][0], x1 = acc[mi][ni][1];
            float x2 = acc[mi][ni][2], x3 = acc[mi][ni][3];
            if (bias) {
                float bb0 = bias[col], bb1 = bias[col + 1];
                x0 += bb0; x1 += bb1; x2 += bb0; x3 += bb1;
            }
            if (act) {
                x0 = 0.5f * x0 * (1.f + erff(x0 * 0.70710678118654752f));
                x1 = 0.5f * x1 * (1.f + erff(x1 * 0.70710678118654752f));
                x2 = 0.5f * x2 * (1.f + erff(x2 * 0.70710678118654752f));
                x3 = 0.5f * x3 * (1.f + erff(x3 * 0.70710678118654752f));
            }
            if (res) {
                x0 += res[(size_t)r0 * N + col];       x1 += res[(size_t)r0 * N + col + 1];
                x2 += res[(size_t)(r0 + 8) * N + col]; x3 += res[(size_t)(r0 + 8) * N + col + 1];
            }
            *(float2*)&C[(size_t)r0 * N + col] = make_float2(x0, x1);
            *(float2*)&C[(size_t)(r0 + 8) * N + col] = make_float2(x2, x3);
        }
    }
}

// ============ fused flash attention (tf32): ctx = softmax(Q K^T / 8) V ============
// Grid: (NL/128, NHB). CTA: 256 threads = 8 warps, each warp owns 16 full rows.
// P never touches SMEM: C-frag -> A-frag relayout done with 4-lane shfl permute.
#define QPITCH 132
#define VPITCH 68
#define SM_Q   0
#define SM_K   (64 * QPITCH)
#define SM_V   (SM_K + 64 * QPITCH)
#define SM_TOT ((SM_V + 128 * VPITCH) * 4)

__global__ __launch_bounds__(256, 1) void flash_tf32() {
    extern __shared__ float sm[];
    float* Qs = sm + SM_Q;
    float* Ks = sm + SM_K;
    float* Vs = sm + SM_V;

    int z = blockIdx.y;
    int sb = z >> 1, h = z & 1;
    const float* Qp = g_QKV + (size_t)sb * NL * 384 + h * 64;
    const float* Kp = Qp + 128;
    const float* Vp = Qp + 256;
    float* Cp = g_CTX + (size_t)sb * NL * ND + h * 64;

    int bm = blockIdx.x * 128;
    int tid = threadIdx.x, lane = tid & 31, warp = tid >> 5;
    int wm = warp * 16;
    int gid = lane >> 2, tig = lane & 3;
    int srcA = (lane & ~3) | (tig >> 1);   // shfl source for cols {tig}
    int srcB = srcA | 2;                   // shfl source for cols {tig+4}
    bool odd = tig & 1;

    {
        int qm = tid & 127, qk = (tid >> 7) * 32;
        #pragma unroll
        for (int i = 0; i < 8; i++) {
            float4 v = *(const float4*)&Qp[(size_t)(bm + qm) * 384 + qk + i * 4];
            Qs[(qk + i * 4 + 0) * QPITCH + qm] = f2tf(v.x * 0.125f);
            Qs[(qk + i * 4 + 1) * QPITCH + qm] = f2tf(v.y * 0.125f);
            Qs[(qk + i * 4 + 2) * QPITCH + qm] = f2tf(v.z * 0.125f);
            Qs[(qk + i * 4 + 3) * QPITCH + qm] = f2tf(v.w * 0.125f);
        }
    }

    float co[8][4] = {};
    float m_r[2] = {-1e30f, -1e30f};
    float l_r[2] = {0.f, 0.f};

    for (int j = 0; j < 4; j++) {
        __syncthreads();
        {
            int kn = tid & 127, kk = (tid >> 7) * 32;
            int krow = j * 128 + kn;
            #pragma unroll
            for (int i = 0; i < 8; i++) {
                float4 v = *(const float4*)&Kp[(size_t)krow * 384 + kk + i * 4];
                Ks[(kk + i * 4 + 0) * QPITCH + kn] = f2tf(v.x);
                Ks[(kk + i * 4 + 1) * QPITCH + kn] = f2tf(v.y);
                Ks[(kk + i * 4 + 2) * QPITCH + kn] = f2tf(v.z);
                Ks[(kk + i * 4 + 3) * QPITCH + kn] = f2tf(v.w);
            }
            int vn = tid >> 1, vc = (tid & 1) * 32;
            int vrow = j * 128 + vn;
            #pragma unroll
            for (int i = 0; i < 8; i++) {
                float4 v = *(const float4*)&Vp[(size_t)vrow * 384 + vc + i * 4];
                float4 w;
                w.x = f2tf(v.x); w.y = f2tf(v.y); w.z = f2tf(v.z); w.w = f2tf(v.w);
                *(float4*)&Vs[vn * VPITCH + vc + i * 4] = w;
            }
        }
        __syncthreads();

        // ---- S = Q @ K^T (warp tile 16 x 128) ----
        float cs[16][4] = {};
        #pragma unroll
        for (int kk = 0; kk < 64; kk += 8) {
            unsigned af[4];
            int mb = wm + gid;
            af[0] = __float_as_uint(Qs[(kk + tig) * QPITCH + mb]);
            af[1] = __float_as_uint(Qs[(kk + tig) * QPITCH + mb + 8]);
            af[2] = __float_as_uint(Qs[(kk + tig + 4) * QPITCH + mb]);
            af[3] = __float_as_uint(Qs[(kk + tig + 4) * QPITCH + mb + 8]);
            #pragma unroll
            for (int ni = 0; ni < 16; ni++) {
                unsigned bf[2];
                int n = ni * 8 + gid;
                bf[0] = __float_as_uint(Ks[(kk + tig) * QPITCH + n]);
                bf[1] = __float_as_uint(Ks[(kk + tig + 4) * QPITCH + n]);
                mma_tf32(cs[ni], af, bf);
            }
        }

        // ---- online softmax (rows fully inside warp) ----
        float tm0 = -1e30f, tm1 = -1e30f;
        #pragma unroll
        for (int ni = 0; ni < 16; ni++) {
            tm0 = fmaxf(tm0, fmaxf(cs[ni][0], cs[ni][1]));
            tm1 = fmaxf(tm1, fmaxf(cs[ni][2], cs[ni][3]));
        }
        tm0 = fmaxf(tm0, __shfl_xor_sync(0xffffffffu, tm0, 1));
        tm0 = fmaxf(tm0, __shfl_xor_sync(0xffffffffu, tm0, 2));
        tm1 = fmaxf(tm1, __shfl_xor_sync(0xffffffffu, tm1, 1));
        tm1 = fmaxf(tm1, __shfl_xor_sync(0xffffffffu, tm1, 2));
        float nm0 = fmaxf(m_r[0], tm0);
        float nm1 = fmaxf(m_r[1], tm1);
        float a0 = __expf(m_r[0] - nm0);
        float a1 = __expf(m_r[1] - nm1);
        float ts0 = 0.f, ts1 = 0.f;
        #pragma unroll
        for (int ni = 0; ni < 16; ni++) {
            cs[ni][0] = __expf(cs[ni][0] - nm0);
            cs[ni][1] = __expf(cs[ni][1] - nm0);
            cs[ni][2] = __expf(cs[ni][2] - nm1);
            cs[ni][3] = __expf(cs[ni][3] - nm1);
            ts0 += cs[ni][0] + cs[ni][1];
            ts1 += cs[ni][2] + cs[ni][3];
        }
        ts0 += __shfl_xor_sync(0xffffffffu, ts0, 1);
        ts0 += __shfl_xor_sync(0xffffffffu, ts0, 2);
        ts1 += __shfl_xor_sync(0xffffffffu, ts1, 1);
        ts1 += __shfl_xor_sync(0xffffffffu, ts1, 2);
        l_r[0] = l_r[0] * a0 + ts0;
        l_r[1] = l_r[1] * a1 + ts1;
        m_r[0] = nm0;
        m_r[1] = nm1;
        #pragma unroll
        for (int ni = 0; ni < 8; ni++) {
            co[ni][0] *= a0; co[ni][1] *= a0;
            co[ni][2] *= a1; co[ni][3] *= a1;
        }

        // ---- O += P @ V: A-frags built from cs via 4-lane shfl permute ----
        #pragma unroll
        for (int kc = 0; kc < 16; kc++) {        // k-chunk = keys [kc*8, kc*8+8)
            float v00 = __shfl_sync(0xffffffffu, cs[kc][0], srcA);
            float v01 = __shfl_sync(0xffffffffu, cs[kc][1], srcA);
            float v10 = __shfl_sync(0xffffffffu, cs[kc][2], srcA);
            float v11 = __shfl_sync(0xffffffffu, cs[kc][3], srcA);
            float v20 = __shfl_sync(0xffffffffu, cs[kc][0], srcB);
            float v21 = __shfl_sync(0xffffffffu, cs[kc][1], srcB);
            float v30 = __shfl_sync(0xffffffffu, cs[kc][2], srcB);
            float v31 = __shfl_sync(0xffffffffu, cs[kc][3], srcB);
            unsigned af[4];
            af[0] = __float_as_uint(f2tf(odd ? v01 : v00));  // P[gid][8kc+tig]
            af[1] = __float_as_uint(f2tf(odd ? v11 : v10));  // P[gid+8][8kc+tig]
            af[2] = __float_as_uint(f2tf(odd ? v21 : v20));  // P[gid][8kc+tig+4]
            af[3] = __float_as_uint(f2tf(odd ? v31 : v30));  // P[gid+8][8kc+tig+4]
            int kk = kc * 8;
            #pragma unroll
            for (int ni = 0; ni < 8; ni++) {
                unsigned bf[2];
                int n = ni * 8 + gid;
                bf[0] = __float_as_uint(Vs[(kk + tig) * VPITCH + n]);
                bf[1] = __float_as_uint(Vs[(kk + tig + 4) * VPITCH + n]);
                mma_tf32(co[ni], af, bf);
            }
        }
    }

    {
        float inv0 = 1.f / l_r[0];
        float inv1 = 1.f / l_r[1];
        int r0 = bm + wm + gid;
        #pragma unroll
        for (int ni = 0; ni < 8; ni++) {
            int col = ni * 8 + tig * 2;
            *(float2*)&Cp[(size_t)r0 * ND + col] =
                make_float2(co[ni][0] * inv0, co[ni][1] * inv0);
            *(float2*)&Cp[(size_t)(r0 + 8) * ND + col] =
                make_float2(co[ni][2] * inv1, co[ni][3] * inv1);
        }
    }
}

// ---------------- launch ----------------
extern "C" void kernel_launch(void* const* d_in, const int* in_sizes, int n_in,
                              void* d_out, int out_size) {
    const int*   src    = (const int*)d_in[0];
    const int*   dst    = (const int*)d_in[1];
    const float* w1     = (const float*)d_in[2];
    const float* b1     = (const float*)d_in[3];
    const float* w2     = (const float*)d_in[4];
    const float* b2     = (const float*)d_in[5];
    const float* proj_w = (const float*)d_in[6];
    const float* proj_b = (const float*)d_in[7];
    const float* ln1_g  = (const float*)d_in[8];
    const float* ln1_b  = (const float*)d_in[9];
    const float* w_qkv  = (const float*)d_in[10];
    const float* b_qkv  = (const float*)d_in[11];
    const float* w_o    = (const float*)d_in[12];
    const float* b_o    = (const float*)d_in[13];
    const float* ln2_g  = (const float*)d_in[14];
    const float* ln2_b  = (const float*)d_in[15];
    const float* w_ff1  = (const float*)d_in[16];
    const float* b_ff1  = (const float*)d_in[17];
    const float* w_ff2  = (const float*)d_in[18];
    const float* b_ff2  = (const float*)d_in[19];
    float* out = (float*)d_out;

    cudaFuncSetAttribute(flash_tf32, cudaFuncAttributeMaxDynamicSharedMemorySize, SM_TOT);
    cudaFuncSetAttribute(gemm_tf32, cudaFuncAttributeMaxDynamicSharedMemorySize, GEMM_SMEM);

    // precompute fused encode+proj table
    k_W    <<<ND, ND>>>(w2, proj_w);
    k_bias <<<1, ND>>>(b2, proj_w, proj_b);
    k_table<<<513, ND>>>(w1, b1);

    // co-occurrence counts + feature build (both streams)
    k_cooc<<<NB, NL>>>(src, dst);
    k_feat<<<(NTOK * ND) / 256, 256>>>();

    // transformer (both streams batched: 65536 tokens)
    k_ln<<<NTOK, ND>>>(BUF_X, BUF_H, ln1_g, ln1_b);
    gemm_tf32<<<dim3(3, NTOK / 128), 256, GEMM_SMEM>>>(BUF_H, w_qkv, b_qkv, -1, BUF_QKV,
                                                       nullptr, NTOK, 384, 128, 0);
    flash_tf32<<<dim3(NL / 128, NHB), 256, SM_TOT>>>();
    gemm_tf32<<<dim3(1, NTOK / 128), 256, GEMM_SMEM>>>(BUF_CTX, w_o, b_o, BUF_X, BUF_X,
                                                       nullptr, NTOK, 128, 128, 0);
    k_ln<<<NTOK, ND>>>(BUF_X, BUF_H, ln2_g, ln2_b);
    gemm_tf32<<<dim3(4, NTOK / 128), 256, GEMM_SMEM>>>(BUF_H, w_ff1, b_ff1, -1, BUF_FF,
                                                       nullptr, NTOK, 512, 128, 1);
    gemm_tf32<<<dim3(1, NTOK / 128), 256, GEMM_SMEM>>>(BUF_FF, w_ff2, b_ff2, BUF_X, BUF_X,
                                                       out, NTOK, 128, 512, 0);
}

// round 10
// speedup vs baseline: 2.3551x; 1.1138x over previous
#include <cuda_runtime.h>
#include <math.h>

#define NB    64
#define NL    512
#define ND    128
#define TOKS  32768          // B*L per stream
#define NTOK  65536          // 2*B*L
#define NHB   256            // 2*B*H attention batches

// ---------------- scratch (device globals; no allocation allowed) ----------------
__device__ int   g_cnt[NTOK * 2];
__device__ float g_W[ND * ND];
__device__ float g_biasT[ND];
__device__ float g_T2[513 * ND];
__device__ float g_X[(size_t)NTOK * ND];
__device__ float g_H[(size_t)NTOK * ND];
__device__ float g_QKV[(size_t)NTOK * 3 * ND];
__device__ float g_CTX[(size_t)NTOK * ND];
__device__ float g_FF[(size_t)NTOK * 4 * ND];
__device__ float g_WR[196608];   // pre-rounded weights: QKV | WO | FF1 | FF2

#define WR_QKV 0
#define WR_WO  49152
#define WR_FF1 65536
#define WR_FF2 131072

#define BUF_X    0
#define BUF_H    1
#define BUF_QKV  2
#define BUF_CTX  3
#define BUF_FF   4
__device__ __forceinline__ float* buf(int id) {
    switch (id) {
        case BUF_X:   return g_X;
        case BUF_H:   return g_H;
        case BUF_QKV: return g_QKV;
        case BUF_CTX: return g_CTX;
        default:      return g_FF;
    }
}

// fp32 -> tf32 (round to nearest)
__device__ __forceinline__ float f2tf(float x) {
    unsigned r;
    asm("cvt.rna.tf32.f32 %0, %1;" : "=r"(r) : "f"(x));
    return __uint_as_float(r);
}

__device__ __forceinline__ void mma_tf32(float* c, const unsigned* a, const unsigned* b) {
    asm volatile(
        "mma.sync.aligned.m16n8k8.row.col.f32.tf32.tf32.f32 "
        "{%0,%1,%2,%3}, {%4,%5,%6,%7}, {%8,%9}, {%0,%1,%2,%3};"
        : "+f"(c[0]), "+f"(c[1]), "+f"(c[2]), "+f"(c[3])
        : "r"(a[0]), "r"(a[1]), "r"(a[2]), "r"(a[3]), "r"(b[0]), "r"(b[1]));
}

__device__ __forceinline__ void cp_async16(float* smem_dst, const float* gsrc) {
    unsigned saddr = (unsigned)__cvta_generic_to_shared(smem_dst);
    asm volatile("cp.async.cg.shared.global [%0], [%1], 16;" :: "r"(saddr), "l"(gsrc));
}

// fast exact-gelu: Abramowitz-Stegun 7.1.26 erf (abs err 1.5e-7)
__device__ __forceinline__ float gelu_f(float x) {
    float z  = x * 0.70710678118654752f;
    float az = fabsf(z);
    float t  = __fdividef(1.f, fmaf(0.3275911f, az, 1.f));
    float p  = t * (0.254829592f + t * (-0.284496736f + t * (1.421413741f +
               t * (-1.453152027f + t * 1.061405429f))));
    float er = copysignf(1.f - p * __expf(-z * z), z);
    return 0.5f * x * (1.f + er);
}

// ---------------- tiny precompute kernels ----------------
__global__ void k_rnd(const float* __restrict__ s, int off, int n) {
    int i = blockIdx.x * 256 + threadIdx.x;
    if (i < n) g_WR[off + i] = f2tf(s[i]);
}

__global__ void k_W(const float* __restrict__ w2, const float* __restrict__ proj_w) {
    int k = blockIdx.x, d = threadIdx.x;
    float acc = 0.f;
    #pragma unroll 8
    for (int j = 0; j < ND; j++) acc += w2[k * ND + j] * proj_w[j * ND + d];
    g_W[k * ND + d] = acc;
}

__global__ void k_bias(const float* __restrict__ b2, const float* __restrict__ proj_w,
                       const float* __restrict__ proj_b) {
    int d = threadIdx.x;
    float acc = proj_b[d];
    #pragma unroll 8
    for (int k = 0; k < ND; k++) acc += 2.f * b2[k] * proj_w[k * ND + d];
    g_biasT[d] = acc;
}

__global__ void k_table(const float* __restrict__ w1, const float* __restrict__ b1) {
    __shared__ float h[ND];
    int c = blockIdx.x, d = threadIdx.x;
    h[d] = fmaxf((float)c * w1[d] + b1[d], 0.f);
    __syncthreads();
    float acc = 0.5f * g_biasT[d];
    #pragma unroll 8
    for (int k = 0; k < ND; k++) acc += h[k] * g_W[k * ND + d];
    g_T2[c * ND + d] = acc;
}

// ---------------- co-occurrence counts ----------------
__global__ void k_cooc(const int* __restrict__ src, const int* __restrict__ dst) {
    __shared__ int ss[NL], dd[NL];
    int b = blockIdx.x, i = threadIdx.x;
    ss[i] = src[b * NL + i];
    dd[i] = dst[b * NL + i];
    __syncthreads();
    int qs = ss[i], qd = dd[i];
    int css = 0, csd = 0, cds = 0, cdd = 0;
    #pragma unroll 8
    for (int j = 0; j < NL; j++) {
        int s = ss[j], t = dd[j];
        css += (qs == s); csd += (qs == t);
        cds += (qd == s); cdd += (qd == t);
    }
    if (qs == 0) { css = 0; csd = 0; }
    if (qd == 0) { cds = 0; cdd = 0; }
    int ts = b * NL + i, td = TOKS + b * NL + i;
    g_cnt[ts * 2 + 0] = css; g_cnt[ts * 2 + 1] = csd;
    g_cnt[td * 2 + 0] = cds; g_cnt[td * 2 + 1] = cdd;
}

__global__ void k_feat() {
    int idx = blockIdx.x * 256 + threadIdx.x;
    int t = idx >> 7, d = idx & 127;
    int c0 = g_cnt[t * 2], c1 = g_cnt[t * 2 + 1];
    g_X[idx] = g_T2[c0 * ND + d] + g_T2[c1 * ND + d];
}

// ---------------- layernorm (output pre-rounded to tf32: GEMM A-side) ----------------
__global__ void k_ln(int xid, int yid,
                     const float* __restrict__ g, const float* __restrict__ b) {
    const float* x = buf(xid);
    float* y = buf(yid);
    int row = blockIdx.x, t = threadIdx.x;
    float v = x[(size_t)row * ND + t];
    __shared__ float sh[4];
    float s = v;
    for (int o = 16; o; o >>= 1) s += __shfl_xor_sync(0xffffffffu, s, o);
    int w = t >> 5;
    if ((t & 31) == 0) sh[w] = s;
    __syncthreads();
    float mu = (sh[0] + sh[1] + sh[2] + sh[3]) * (1.f / 128.f);
    __syncthreads();
    float dlt = v - mu;
    float s2 = dlt * dlt;
    for (int o = 16; o; o >>= 1) s2 += __shfl_xor_sync(0xffffffffu, s2, o);
    if ((t & 31) == 0) sh[w] = s2;
    __syncthreads();
    float var = (sh[0] + sh[1] + sh[2] + sh[3]) * (1.f / 128.f);
    float r = rsqrtf(var + 1e-5f);
    y[(size_t)row * ND + t] = f2tf(dlt * r * g[t] + b[t]);
}

// ============ tf32 GEMM, 3-stage cp.async, NO in-loop cvt (operands pre-rounded) ============
// Block tile 128x128, BK=16, 256 thr = 8 warps (4m x 2n), warp tile 32x64.
#define AP 20
#define BP 136
#define NSTG 3
#define GEMM_SMEM ((NSTG * 128 * AP + NSTG * 16 * BP) * 4)
__global__ __launch_bounds__(256, 2) void gemm_tf32(
        int Aid, const float* __restrict__ Bm,
        const float* __restrict__ bias, int resid,
        int Cid, float* __restrict__ cext,
        int M, int N, int K, int act, int rndC, int kscale) {
    const float* A = buf(Aid);
    const float* res = (resid >= 0) ? buf(resid) : nullptr;
    float* C = cext ? cext : buf(Cid);
    extern __shared__ float gsm[];
    float* Asm = gsm;
    float* Bsm = gsm + NSTG * 128 * AP;
    int tid = threadIdx.x;
    int lane = tid & 31, warp = tid >> 5;
    int wm = (warp >> 1) * 32, wn = (warp & 1) * 64;
    int gid = lane >> 2, tig = lane & 3;
    int bm = blockIdx.y * 128, bn = blockIdx.x * 128;

    int a_row = tid >> 1, a_kc = (tid & 1) * 8;
    int b_row = tid >> 4, b_nc = (tid & 15) * 8;

    int nk = K / 16;
    #pragma unroll
    for (int p = 0; p < 2; p++) {
        if (p < nk) {
            int k0 = p * 16;
            const float* ga = &A[(size_t)(bm + a_row) * K + k0 + a_kc];
            cp_async16(&Asm[p * 128 * AP + a_row * AP + a_kc], ga);
            cp_async16(&Asm[p * 128 * AP + a_row * AP + a_kc + 4], ga + 4);
            const float* gb = &Bm[(size_t)(k0 + b_row) * N + bn + b_nc];
            cp_async16(&Bsm[p * 16 * BP + b_row * BP + b_nc], gb);
            cp_async16(&Bsm[p * 16 * BP + b_row * BP + b_nc + 4], gb + 4);
            asm volatile("cp.async.commit_group;");
        }
    }

    float acc[2][8][4] = {};
    for (int it = 0; it < nk; it++) {
        if (it + 1 < nk) asm volatile("cp.async.wait_group 1;");
        else             asm volatile("cp.async.wait_group 0;");
        __syncthreads();
        if (it + 2 < nk) {
            int nxt = (it + 2) % NSTG, k0 = (it + 2) * 16;
            const float* ga = &A[(size_t)(bm + a_row) * K + k0 + a_kc];
            cp_async16(&Asm[nxt * 128 * AP + a_row * AP + a_kc], ga);
            cp_async16(&Asm[nxt * 128 * AP + a_row * AP + a_kc + 4], ga + 4);
            const float* gb = &Bm[(size_t)(k0 + b_row) * N + bn + b_nc];
            cp_async16(&Bsm[nxt * 16 * BP + b_row * BP + b_nc], gb);
            cp_async16(&Bsm[nxt * 16 * BP + b_row * BP + b_nc + 4], gb + 4);
            asm volatile("cp.async.commit_group;");
        }
        const float* As = Asm + (it % NSTG) * 128 * AP;
        const float* Bs = Bsm + (it % NSTG) * 16 * BP;
        #pragma unroll
        for (int kk = 0; kk < 16; kk += 8) {
            unsigned af[2][4], bf[8][2];
            #pragma unroll
            for (int mi = 0; mi < 2; mi++) {
                int mb = wm + mi * 16 + gid;
                af[mi][0] = __float_as_uint(As[mb * AP + kk + tig]);
                af[mi][1] = __float_as_uint(As[(mb + 8) * AP + kk + tig]);
                af[mi][2] = __float_as_uint(As[mb * AP + kk + tig + 4]);
                af[mi][3] = __float_as_uint(As[(mb + 8) * AP + kk + tig + 4]);
            }
            #pragma unroll
            for (int ni = 0; ni < 8; ni++) {
                int n = wn + ni * 8 + gid;
                bf[ni][0] = __float_as_uint(Bs[(kk + tig) * BP + n]);
                bf[ni][1] = __float_as_uint(Bs[(kk + tig + 4) * BP + n]);
            }
            #pragma unroll
            for (int mi = 0; mi < 2; mi++)
                #pragma unroll
                for (int ni = 0; ni < 8; ni++)
                    mma_tf32(acc[mi][ni], af[mi], bf[ni]);
        }
    }

    #pragma unroll
    for (int mi = 0; mi < 2; mi++) {
        int r0 = bm + wm + mi * 16 + gid;
        #pragma unroll
        for (int ni = 0; ni < 8; ni++) {
            int col = bn + wn + ni * 8 + tig * 2;
            float x0 = acc[mi][ni][0], x1 = acc[mi][ni][1];
            float x2 = acc[mi][ni][2], x3 = acc[mi][ni][3];
            if (bias) {
                float bb0 = bias[col], bb1 = bias[col + 1];
                x0 += bb0; x1 += bb1; x2 += bb0; x3 += bb1;
            }
            if (kscale && col >= 128 && col < 256) {
                x0 *= 0.125f; x1 *= 0.125f; x2 *= 0.125f; x3 *= 0.125f;
            }
            if (act) {
                x0 = gelu_f(x0); x1 = gelu_f(x1);
                x2 = gelu_f(x2); x3 = gelu_f(x3);
            }
            if (rndC) {
                x0 = f2tf(x0); x1 = f2tf(x1); x2 = f2tf(x2); x3 = f2tf(x3);
            }
            if (res) {
                x0 += res[(size_t)r0 * N + col];       x1 += res[(size_t)r0 * N + col + 1];
                x2 += res[(size_t)(r0 + 8) * N + col]; x3 += res[(size_t)(r0 + 8) * N + col + 1];
            }
            *(float2*)&C[(size_t)r0 * N + col] = make_float2(x0, x1);
            *(float2*)&C[(size_t)(r0 + 8) * N + col] = make_float2(x2, x3);
        }
    }
}

// ============ fused flash attention (tf32): ctx = softmax(Q K'^T) V ============
// K pre-scaled by 0.125 and Q/K/V pre-rounded at the QKV GEMM epilogue.
// Q/K/V loaded row-major (pitch 68) via cp.async; K/V double-buffered across j.
#define FP 68
#define FQ 0
#define FK (128 * FP)
#define FV (FK + 2 * 128 * FP)
#define SM_TOT ((FV + 2 * 128 * FP) * 4)

__global__ __launch_bounds__(256, 1) void flash_tf32() {
    extern __shared__ float sm[];
    float* Qs = sm + FQ;
    float* Ks = sm + FK;   // [2][128*FP]
    float* Vs = sm + FV;   // [2][128*FP]

    int z = blockIdx.y;
    int sb = z >> 1, h = z & 1;
    const float* Qp = g_QKV + (size_t)sb * NL * 384 + h * 64;
    const float* Kp = Qp + 128;
    const float* Vp = Qp + 256;
    float* Cp = g_CTX + (size_t)sb * NL * ND + h * 64;

    int bm = blockIdx.x * 128;
    int tid = threadIdx.x, lane = tid & 31, warp = tid >> 5;
    int wm = warp * 16;
    int gid = lane >> 2, tig = lane & 3;
    int srcA = (lane & ~3) | (tig >> 1);
    int srcB = srcA | 2;
    bool odd = tig & 1;

    int lrow = tid >> 1, lcol = (tid & 1) * 32;

    // prologue: Q + K0 + V0 via cp.async
    #pragma unroll
    for (int i = 0; i < 8; i++)
        cp_async16(&Qs[lrow * FP + lcol + i * 4],
                   &Qp[(size_t)(bm + lrow) * 384 + lcol + i * 4]);
    #pragma unroll
    for (int i = 0; i < 8; i++)
        cp_async16(&Ks[lrow * FP + lcol + i * 4],
                   &Kp[(size_t)lrow * 384 + lcol + i * 4]);
    #pragma unroll
    for (int i = 0; i < 8; i++)
        cp_async16(&Vs[lrow * FP + lcol + i * 4],
                   &Vp[(size_t)lrow * 384 + lcol + i * 4]);
    asm volatile("cp.async.commit_group;");

    float co[8][4] = {};
    float m_r[2] = {-1e30f, -1e30f};
    float l_r[2] = {0.f, 0.f};

    for (int j = 0; j < 4; j++) {
        asm volatile("cp.async.wait_group 0;");
        __syncthreads();   // stage j visible; buffer (j+1)&1 fully consumed by compute j-1
        if (j + 1 < 4) {
            int nb = (j + 1) & 1;
            int grow = (j + 1) * 128 + lrow;
            #pragma unroll
            for (int i = 0; i < 8; i++)
                cp_async16(&Ks[nb * 128 * FP + lrow * FP + lcol + i * 4],
                           &Kp[(size_t)grow * 384 + lcol + i * 4]);
            #pragma unroll
            for (int i = 0; i < 8; i++)
                cp_async16(&Vs[nb * 128 * FP + lrow * FP + lcol + i * 4],
                           &Vp[(size_t)grow * 384 + lcol + i * 4]);
            asm volatile("cp.async.commit_group;");
        }
        const float* Kc = Ks + (j & 1) * 128 * FP;
        const float* Vc = Vs + (j & 1) * 128 * FP;

        // ---- S = Q @ K'^T (warp tile 16 x 128) ----
        float cs[16][4] = {};
        #pragma unroll
        for (int kk = 0; kk < 64; kk += 8) {
            unsigned af[4];
            int mb = wm + gid;
            af[0] = __float_as_uint(Qs[mb * FP + kk + tig]);
            af[1] = __float_as_uint(Qs[(mb + 8) * FP + kk + tig]);
            af[2] = __float_as_uint(Qs[mb * FP + kk + tig + 4]);
            af[3] = __float_as_uint(Qs[(mb + 8) * FP + kk + tig + 4]);
            #pragma unroll
            for (int ni = 0; ni < 16; ni++) {
                unsigned bf[2];
                int n = ni * 8 + gid;
                bf[0] = __float_as_uint(Kc[n * FP + kk + tig]);
                bf[1] = __float_as_uint(Kc[n * FP + kk + tig + 4]);
                mma_tf32(cs[ni], af, bf);
            }
        }

        // ---- online softmax (rows fully inside warp) ----
        float tm0 = -1e30f, tm1 = -1e30f;
        #pragma unroll
        for (int ni = 0; ni < 16; ni++) {
            tm0 = fmaxf(tm0, fmaxf(cs[ni][0], cs[ni][1]));
            tm1 = fmaxf(tm1, fmaxf(cs[ni][2], cs[ni][3]));
        }
        tm0 = fmaxf(tm0, __shfl_xor_sync(0xffffffffu, tm0, 1));
        tm0 = fmaxf(tm0, __shfl_xor_sync(0xffffffffu, tm0, 2));
        tm1 = fmaxf(tm1, __shfl_xor_sync(0xffffffffu, tm1, 1));
        tm1 = fmaxf(tm1, __shfl_xor_sync(0xffffffffu, tm1, 2));
        float nm0 = fmaxf(m_r[0], tm0);
        float nm1 = fmaxf(m_r[1], tm1);
        float a0 = __expf(m_r[0] - nm0);
        float a1 = __expf(m_r[1] - nm1);
        float ts0 = 0.f, ts1 = 0.f;
        #pragma unroll
        for (int ni = 0; ni < 16; ni++) {
            cs[ni][0] = __expf(cs[ni][0] - nm0);
            cs[ni][1] = __expf(cs[ni][1] - nm0);
            cs[ni][2] = __expf(cs[ni][2] - nm1);
            cs[ni][3] = __expf(cs[ni][3] - nm1);
            ts0 += cs[ni][0] + cs[ni][1];
            ts1 += cs[ni][2] + cs[ni][3];
        }
        ts0 += __shfl_xor_sync(0xffffffffu, ts0, 1);
        ts0 += __shfl_xor_sync(0xffffffffu, ts0, 2);
        ts1 += __shfl_xor_sync(0xffffffffu, ts1, 1);
        ts1 += __shfl_xor_sync(0xffffffffu, ts1, 2);
        l_r[0] = l_r[0] * a0 + ts0;
        l_r[1] = l_r[1] * a1 + ts1;
        m_r[0] = nm0;
        m_r[1] = nm1;
        #pragma unroll
        for (int ni = 0; ni < 8; ni++) {
            co[ni][0] *= a0; co[ni][1] *= a0;
            co[ni][2] *= a1; co[ni][3] *= a1;
        }

        // ---- O += P @ V: A-frags via 4-lane shfl permute ----
        #pragma unroll
        for (int kc = 0; kc < 16; kc++) {
            float v00 = __shfl_sync(0xffffffffu, cs[kc][0], srcA);
            float v01 = __shfl_sync(0xffffffffu, cs[kc][1], srcA);
            float v10 = __shfl_sync(0xffffffffu, cs[kc][2], srcA);
            float v11 = __shfl_sync(0xffffffffu, cs[kc][3], srcA);
            float v20 = __shfl_sync(0xffffffffu, cs[kc][0], srcB);
            float v21 = __shfl_sync(0xffffffffu, cs[kc][1], srcB);
            float v30 = __shfl_sync(0xffffffffu, cs[kc][2], srcB);
            float v31 = __shfl_sync(0xffffffffu, cs[kc][3], srcB);
            unsigned af[4];
            af[0] = __float_as_uint(f2tf(odd ? v01 : v00));
            af[1] = __float_as_uint(f2tf(odd ? v11 : v10));
            af[2] = __float_as_uint(f2tf(odd ? v21 : v20));
            af[3] = __float_as_uint(f2tf(odd ? v31 : v30));
            int kk = kc * 8;
            #pragma unroll
            for (int ni = 0; ni < 8; ni++) {
                unsigned bf[2];
                int n = ni * 8 + gid;
                bf[0] = __float_as_uint(Vc[(kk + tig) * FP + n]);
                bf[1] = __float_as_uint(Vc[(kk + tig + 4) * FP + n]);
                mma_tf32(co[ni], af, bf);
            }
        }
    }

    // ---- normalize and store (pre-rounded: A-side of WO GEMM) ----
    {
        float inv0 = 1.f / l_r[0];
        float inv1 = 1.f / l_r[1];
        int r0 = bm + wm + gid;
        #pragma unroll
        for (int ni = 0; ni < 8; ni++) {
            int col = ni * 8 + tig * 2;
            *(float2*)&Cp[(size_t)r0 * ND + col] =
                make_float2(f2tf(co[ni][0] * inv0), f2tf(co[ni][1] * inv0));
            *(float2*)&Cp[(size_t)(r0 + 8) * ND + col] =
                make_float2(f2tf(co[ni][2] * inv1), f2tf(co[ni][3] * inv1));
        }
    }
}

// ---------------- launch ----------------
extern "C" void kernel_launch(void* const* d_in, const int* in_sizes, int n_in,
                              void* d_out, int out_size) {
    const int*   src    = (const int*)d_in[0];
    const int*   dst    = (const int*)d_in[1];
    const float* w1     = (const float*)d_in[2];
    const float* b1     = (const float*)d_in[3];
    const float* w2     = (const float*)d_in[4];
    const float* b2     = (const float*)d_in[5];
    const float* proj_w = (const float*)d_in[6];
    const float* proj_b = (const float*)d_in[7];
    const float* ln1_g  = (const float*)d_in[8];
    const float* ln1_b  = (const float*)d_in[9];
    const float* w_qkv  = (const float*)d_in[10];
    const float* b_qkv  = (const float*)d_in[11];
    const float* w_o    = (const float*)d_in[12];
    const float* b_o    = (const float*)d_in[13];
    const float* ln2_g  = (const float*)d_in[14];
    const float* ln2_b  = (const float*)d_in[15];
    const float* w_ff1  = (const float*)d_in[16];
    const float* b_ff1  = (const float*)d_in[17];
    const float* w_ff2  = (const float*)d_in[18];
    const float* b_ff2  = (const float*)d_in[19];
    float* out = (float*)d_out;

    cudaFuncSetAttribute(flash_tf32, cudaFuncAttributeMaxDynamicSharedMemorySize, SM_TOT);
    cudaFuncSetAttribute(gemm_tf32, cudaFuncAttributeMaxDynamicSharedMemorySize, GEMM_SMEM);

    // device-side scratch weight pointers
    float* WR;
    {
        void* p; cudaGetSymbolAddress(&p, g_WR); WR = (float*)p;
    }

    // pre-round weights to tf32 (one-time, tiny)
    k_rnd<<<(128 * 384 + 255) / 256, 256>>>(w_qkv, WR_QKV, 128 * 384);
    k_rnd<<<(128 * 128 + 255) / 256, 256>>>(w_o,   WR_WO,  128 * 128);
    k_rnd<<<(128 * 512 + 255) / 256, 256>>>(w_ff1, WR_FF1, 128 * 512);
    k_rnd<<<(512 * 128 + 255) / 256, 256>>>(w_ff2, WR_FF2, 512 * 128);

    // precompute fused encode+proj table
    k_W    <<<ND, ND>>>(w2, proj_w);
    k_bias <<<1, ND>>>(b2, proj_w, proj_b);
    k_table<<<513, ND>>>(w1, b1);

    // co-occurrence counts + feature build (both streams)
    k_cooc<<<NB, NL>>>(src, dst);
    k_feat<<<(NTOK * ND) / 256, 256>>>();

    // transformer (both streams batched: 65536 tokens)
    k_ln<<<NTOK, ND>>>(BUF_X, BUF_H, ln1_g, ln1_b);
    gemm_tf32<<<dim3(3, NTOK / 128), 256, GEMM_SMEM>>>(BUF_H, WR + WR_QKV, b_qkv, -1,
        BUF_QKV, nullptr, NTOK, 384, 128, 0, 1, 1);
    flash_tf32<<<dim3(NL / 128, NHB), 256, SM_TOT>>>();
    gemm_tf32<<<dim3(1, NTOK / 128), 256, GEMM_SMEM>>>(BUF_CTX, WR + WR_WO, b_o, BUF_X,
        BUF_X, nullptr, NTOK, 128, 128, 0, 0, 0);
    k_ln<<<NTOK, ND>>>(BUF_X, BUF_H, ln2_g, ln2_b);
    gemm_tf32<<<dim3(4, NTOK / 128), 256, GEMM_SMEM>>>(BUF_H, WR + WR_FF1, b_ff1, -1,
        BUF_FF, nullptr, NTOK, 512, 128, 1, 1, 0);
    gemm_tf32<<<dim3(1, NTOK / 128), 256, GEMM_SMEM>>>(BUF_FF, WR + WR_FF2, b_ff2, BUF_X,
        BUF_X, out, NTOK, 128, 512, 0, 0, 0);
}